// round 11
// baseline (speedup 1.0000x reference)
#include <cuda_runtime.h>
#include <cuda_fp16.h>
#include <cstdint>

// ---------------------------------------------------------------------------
// Problem dims
// ---------------------------------------------------------------------------
#define Bv   128
#define LTv  96
#define LIv  64
#define Dv   1024
#define Hv   4
#define DHv  256
#define DTv  1024
#define DIv  2048
#define BHv  (Bv * Hv)    // 512

#define NEGF (-2147483648.0f)   // -2^31

// ---------------------------------------------------------------------------
// Scratch buffers
// ---------------------------------------------------------------------------
static __device__ __half g_tE16[(size_t)Bv * LTv * DTv];
static __device__ __half g_iE16[(size_t)Bv * LIv * DIv];
static __device__ __half g_Pt16[(size_t)Bv * LTv * Dv];
static __device__ __half g_PairT[(size_t)Bv * LTv * 2048];   // Pt @ [ta_Wk | ia_Wq] = [KT | QI]
static __device__ __half g_VT[(size_t)Bv * LTv * Dv];
static __device__ __half g_PiVI[(size_t)Bv * LIv * 2048];    // iE @ [W_ip | ia_Wv] = [Pi | VI]
static __device__ __half g_PairI[(size_t)Bv * LIv * 2048];   // Pi @ [ta_Wq | ia_Wk] = [QT | KI]
// branch T (text_att -> out_text), Mi rows
static __device__ __half g_AOT[(size_t)Bv * LIv * Dv];
static __device__ __half g_XT[(size_t)Bv * LIv * Dv];
static __device__ __half g_QKVT[(size_t)Bv * LIv * Dv * 3];
static __device__ __half g_CTh[(size_t)Bv * LIv * Dv];
// branch I (image_att -> out_img), Mt rows
static __device__ __half g_AOI[(size_t)Bv * LTv * Dv];
static __device__ __half g_XI[(size_t)Bv * LTv * Dv];
static __device__ __half g_QKVI[(size_t)Bv * LTv * Dv * 3];
static __device__ __half g_CIh[(size_t)Bv * LTv * Dv];
// weight arena: 20 x 1M-half slots (slot map in kernel_launch)
static __device__ __half g_Wh[(size_t)20 * 1024 * 1024];
// padded image-proj bias [b_ip | 0]
static __device__ float g_bPI[2048];

// ---------------------------------------------------------------------------
// PTX helpers
// ---------------------------------------------------------------------------
__device__ __forceinline__ uint32_t smem_u32(const void* p) {
    uint32_t a;
    asm("{ .reg .u64 t; cvta.to.shared.u64 t, %1; cvt.u32.u64 %0, t; }" : "=r"(a) : "l"(p));
    return a;
}
#define CP_COMMIT() asm volatile("cp.async.commit_group;" ::: "memory")
#define CP_WAIT1()  asm volatile("cp.async.wait_group 1;" ::: "memory")
#define CP_WAIT0()  asm volatile("cp.async.wait_group 0;" ::: "memory")

__device__ __forceinline__ void cp16(uint32_t dst, const void* src) {
    asm volatile("cp.async.cg.shared.global [%0], [%1], 16;" :: "r"(dst), "l"(src));
}
__device__ __forceinline__ void cp16z(uint32_t dst, const void* src, int sz) {
    asm volatile("cp.async.cg.shared.global [%0], [%1], 16, %2;"
                 :: "r"(dst), "l"(src), "r"(sz));
}
__device__ __forceinline__ void ldsm4(uint32_t& r0, uint32_t& r1, uint32_t& r2,
                                      uint32_t& r3, uint32_t addr) {
    asm volatile("ldmatrix.sync.aligned.m8n8.x4.shared.b16 {%0,%1,%2,%3}, [%4];"
                 : "=r"(r0), "=r"(r1), "=r"(r2), "=r"(r3) : "r"(addr));
}
__device__ __forceinline__ void ldsm4t(uint32_t& r0, uint32_t& r1, uint32_t& r2,
                                       uint32_t& r3, uint32_t addr) {
    asm volatile("ldmatrix.sync.aligned.m8n8.x4.trans.shared.b16 {%0,%1,%2,%3}, [%4];"
                 : "=r"(r0), "=r"(r1), "=r"(r2), "=r"(r3) : "r"(addr));
}
__device__ __forceinline__ void ldsm2(uint32_t& r0, uint32_t& r1, uint32_t addr) {
    asm volatile("ldmatrix.sync.aligned.m8n8.x2.shared.b16 {%0,%1}, [%2];"
                 : "=r"(r0), "=r"(r1) : "r"(addr));
}
__device__ __forceinline__ void mma_f16(float* c, uint32_t a0, uint32_t a1,
                                        uint32_t a2, uint32_t a3,
                                        uint32_t b0, uint32_t b1) {
    asm volatile(
        "mma.sync.aligned.m16n8k16.row.col.f32.f16.f16.f32 "
        "{%0,%1,%2,%3}, {%4,%5,%6,%7}, {%8,%9}, {%0,%1,%2,%3};"
        : "+f"(c[0]), "+f"(c[1]), "+f"(c[2]), "+f"(c[3])
        : "r"(a0), "r"(a1), "r"(a2), "r"(a3), "r"(b0), "r"(b1));
}

// ---------------------------------------------------------------------------
// fp16 mma GEMM: C[M,N] = A16[M,K(lda)] @ W[K,N] (+bias fp32).
// CTA 128x128, 8 warps, warp tile 64x32, BK=64, 3-stage cp.async.
// ---------------------------------------------------------------------------
#define STAGE_BYTES 32768u
#define NSTAGE      3
#define SMEM_BYTES  (NSTAGE * STAGE_BYTES)

__device__ __forceinline__ void load_chunk_h(uint32_t sb, int s,
                                             const __half* __restrict__ A, int lda,
                                             const __half* __restrict__ Wt,
                                             int K, int kk, int bm, int bn, int tid)
{
    const uint32_t uA = sb + (uint32_t)s * STAGE_BYTES;
    const uint32_t uB = uA + 16384u;
#pragma unroll
    for (int j = 0; j < 4; j++) {
        int idx = tid + 256 * j;
        int row = idx >> 3, seg = idx & 7;
        cp16(uA + row * 128 + ((seg ^ (row & 7)) << 4),
             A + (size_t)(bm + row) * lda + kk + seg * 8);
    }
#pragma unroll
    for (int j = 0; j < 4; j++) {
        int idx = tid + 256 * j;
        int row = idx >> 3, seg = idx & 7;
        cp16(uB + row * 128 + ((seg ^ (row & 7)) << 4),
             Wt + (size_t)(bn + row) * K + kk + seg * 8);
    }
    CP_COMMIT();
}

__global__ void __launch_bounds__(256, 2)
hgemm_kernel(const __half* __restrict__ A, int lda,
             const __half* __restrict__ Wt,
             const float* __restrict__ bias, float* __restrict__ C,
             __half* __restrict__ C16, int M, int N, int K)
{
    extern __shared__ char smc[];
    const uint32_t sb = smem_u32(smc);
    const int tid  = threadIdx.x;
    const int lane = tid & 31;
    const int warp = tid >> 5;
    const int wm   = warp >> 2;
    const int wn   = warp & 3;
    const int bm   = blockIdx.y * 128;
    const int bn   = blockIdx.x * 128;

    const int lane15 = lane & 15;
    const int hi     = lane >> 4;

    int arow[4], brow[2];
#pragma unroll
    for (int mi = 0; mi < 4; mi++) arow[mi] = wm * 64 + mi * 16 + lane15;
#pragma unroll
    for (int nb = 0; nb < 2; nb++) brow[nb] = wn * 32 + nb * 16 + lane15;

    float acc[4][4][4];
#pragma unroll
    for (int mi = 0; mi < 4; mi++)
#pragma unroll
        for (int ni = 0; ni < 4; ni++)
#pragma unroll
            for (int r = 0; r < 4; r++) acc[mi][ni][r] = 0.0f;

    const int NC = K >> 6;
    load_chunk_h(sb, 0, A, lda, Wt, K, 0,  bm, bn, tid);
    load_chunk_h(sb, 1, A, lda, Wt, K, 64, bm, bn, tid);

    int sc = 0, sl = 2;
    for (int i = 0; i < NC; i++) {
        if (i < NC - 1) CP_WAIT1(); else CP_WAIT0();
        __syncthreads();

        if (i + 2 < NC) {
            load_chunk_h(sb, sl, A, lda, Wt, K, (i + 2) * 64, bm, bn, tid);
            if (++sl == NSTAGE) sl = 0;
        }

        const uint32_t uA = sb + (uint32_t)sc * STAGE_BYTES;
        const uint32_t uB = uA + 16384u;
        if (++sc == NSTAGE) sc = 0;

#pragma unroll
        for (int ks = 0; ks < 4; ks++) {
            const int sg = ks * 2 + hi;
            uint32_t bf[4][2];
#pragma unroll
            for (int nb = 0; nb < 2; nb++) {
                uint32_t r0, r1, r2, r3;
                ldsm4(r0, r1, r2, r3,
                      uB + brow[nb] * 128 + ((sg ^ (brow[nb] & 7)) << 4));
                bf[nb * 2][0]     = r0; bf[nb * 2][1]     = r2;
                bf[nb * 2 + 1][0] = r1; bf[nb * 2 + 1][1] = r3;
            }
#pragma unroll
            for (int mi = 0; mi < 4; mi++) {
                uint32_t a0, a1, a2, a3;
                ldsm4(a0, a1, a2, a3,
                      uA + arow[mi] * 128 + ((sg ^ (arow[mi] & 7)) << 4));
#pragma unroll
                for (int ni = 0; ni < 4; ni++)
                    mma_f16(acc[mi][ni], a0, a1, a2, a3, bf[ni][0], bf[ni][1]);
            }
        }
    }

    const int qr = lane >> 2, qc = lane & 3;
#pragma unroll
    for (int mi = 0; mi < 4; mi++) {
        const int row = bm + wm * 64 + mi * 16 + qr;
#pragma unroll
        for (int ni = 0; ni < 4; ni++) {
            const int col = bn + wn * 32 + ni * 8 + qc * 2;
            float2 v0 = make_float2(acc[mi][ni][0], acc[mi][ni][1]);
            float2 v1 = make_float2(acc[mi][ni][2], acc[mi][ni][3]);
            if (bias) {
                const float2 bz = *(const float2*)(bias + col);
                v0.x += bz.x; v0.y += bz.y;
                v1.x += bz.x; v1.y += bz.y;
            }
            if (C) {
                *(float2*)(C + (size_t)row * N + col)       = v0;
                *(float2*)(C + (size_t)(row + 8) * N + col) = v1;
            }
            if (C16) {
                __half2 h0 = __floats2half2_rn(v0.x, v0.y);
                __half2 h1 = __floats2half2_rn(v1.x, v1.y);
                *(__half2*)(C16 + (size_t)row * N + col)       = h0;
                *(__half2*)(C16 + (size_t)(row + 8) * N + col) = h1;
            }
        }
    }
}

// ---------------------------------------------------------------------------
// fp32 -> fp16 convert
// ---------------------------------------------------------------------------
__global__ void __launch_bounds__(256)
f2h_kernel(const float4* __restrict__ src, uint2* __restrict__ dst, int n4)
{
    const int i = blockIdx.x * 256 + threadIdx.x;
    if (i < n4) {
        float4 v = src[i];
        __half2 h0 = __floats2half2_rn(v.x, v.y);
        __half2 h1 = __floats2half2_rn(v.z, v.w);
        uint2 o;
        o.x = *(uint32_t*)&h0;
        o.y = *(uint32_t*)&h1;
        dst[i] = o;
    }
}

// ---------------------------------------------------------------------------
// Batched weight transpose + fp16: dst[n][k] = fp16(src[k][n]), src [K,1024]
// ---------------------------------------------------------------------------
struct SrcArr4  { const float* p[4]; };
struct SrcArr2  { const float* p[2]; };
struct SrcArr10 { const float* p[10]; };

template <typename SA>
__global__ void __launch_bounds__(256)
transpose_kernel(SA srcs, __half* __restrict__ dstbase, int K, size_t dst_stride)
{
    __shared__ float t[32][33];
    const float* src = srcs.p[blockIdx.z];
    __half* dst = dstbase + (size_t)blockIdx.z * dst_stride;
    const int n0 = blockIdx.x * 32, k0 = blockIdx.y * 32;
    const int tx = threadIdx.x, ty = threadIdx.y;
#pragma unroll
    for (int j = 0; j < 32; j += 8)
        t[ty + j][tx] = src[(size_t)(k0 + ty + j) * 1024 + n0 + tx];
    __syncthreads();
#pragma unroll
    for (int j = 0; j < 32; j += 8)
        dst[(size_t)(n0 + ty + j) * K + k0 + tx] = __float2half(t[tx][ty + j]);
}

__global__ void __launch_bounds__(256)
bias_pad_kernel(const float* __restrict__ b, float* __restrict__ out)
{
    const int n = blockIdx.x * 256 + threadIdx.x;   // 0..2047
    out[n] = (n < 1024) ? b[n] : 0.0f;
}

// ---------------------------------------------------------------------------
// Tensor-core fused attention (unchanged -- known good).
// ---------------------------------------------------------------------------
#define ATTN_SMEM2 90496

__device__ __forceinline__ void attn_load_qk(uint32_t sb, int st, int c,
        const __half* __restrict__ Q, int sq, const __half* __restrict__ K, int sk,
        int b, int h, int Lq, int Lk, int tid)
{
    const uint32_t uq = sb + (uint32_t)st * 24576u;
    const uint32_t uk = uq + 12288u;
#pragma unroll
    for (int j = 0; j < 3; j++) {
        const int idx = tid + 256 * j;
        const int row = idx >> 3, seg = idx & 7;
        const uint32_t off = row * 128 + ((seg ^ (row & 7)) << 4);
        {
            const int rq = (row < Lq) ? row : 0;
            cp16z(uq + off, Q + (size_t)(b * Lq + rq) * sq + h * DHv + c * 64 + seg * 8,
                  (row < Lq) ? 16 : 0);
        }
        {
            const int rk = (row < Lk) ? row : 0;
            cp16z(uk + off, K + (size_t)(b * Lk + rk) * sk + h * DHv + c * 64 + seg * 8,
                  (row < Lk) ? 16 : 0);
        }
    }
    CP_COMMIT();
}

__global__ void __launch_bounds__(256)
attn_mma_kernel(const __half* __restrict__ Q, int sq,
                const __half* __restrict__ K, int sk,
                const __half* __restrict__ V, int sv,
                __half* __restrict__ AO,
                const int* __restrict__ qm, const int* __restrict__ km,
                int Lq, int Lk)
{
    extern __shared__ char smb[];
    const uint32_t sb = smem_u32(smb);
    float*  Ss = (float*)(smb + 53248);
    __half* P  = (__half*)smb;           // row stride 104 halves
    const uint32_t uP = sb;
    const uint32_t uV = sb + 20480u;

    const int bh = blockIdx.x;
    const int b  = bh >> 2;
    const int h  = bh & 3;
    const int tid  = threadIdx.x;
    const int lane = tid & 31;
    const int warp = tid >> 5;
    const int wm   = warp >> 2;
    const int wn   = warp & 3;
    const int lane15 = lane & 15;
    const int hi     = lane >> 4;
    const int qr = lane >> 2, qc = lane & 3;

    // phase 1: scores = QK^T
    float acc[3][3][4];
#pragma unroll
    for (int mi = 0; mi < 3; mi++)
#pragma unroll
        for (int ni = 0; ni < 3; ni++)
#pragma unroll
            for (int r = 0; r < 4; r++) acc[mi][ni][r] = 0.0f;

    attn_load_qk(sb, 0, 0, Q, sq, K, sk, b, h, Lq, Lk, tid);
    attn_load_qk(sb, 1, 1, Q, sq, K, sk, b, h, Lq, Lk, tid);

    for (int c = 0; c < 4; c++) {
        const int st = c & 1;
        if (c < 3) CP_WAIT1(); else CP_WAIT0();
        __syncthreads();

        const uint32_t uq = sb + (uint32_t)st * 24576u;
        const uint32_t uk = uq + 12288u;

#pragma unroll
        for (int ks = 0; ks < 4; ks++) {
            const int sg = ks * 2 + hi;
            uint32_t aT[3][4];
#pragma unroll
            for (int mi = 0; mi < 3; mi++) {
                const int row = wm * 48 + mi * 16 + lane15;
                ldsm4(aT[mi][0], aT[mi][1], aT[mi][2], aT[mi][3],
                      uq + row * 128 + ((sg ^ (row & 7)) << 4));
            }
            uint32_t bT[3][2];
            {
                const int row = wn * 24 + lane15;
                uint32_t r0, r1, r2, r3;
                ldsm4(r0, r1, r2, r3, uk + row * 128 + ((sg ^ (row & 7)) << 4));
                bT[0][0] = r0; bT[0][1] = r2;
                bT[1][0] = r1; bT[1][1] = r3;
            }
            {
                const int row2 = wn * 24 + 16 + (lane & 7);
                const int sg2  = ks * 2 + ((lane >> 3) & 1);
                uint32_t r0, r1;
                ldsm2(r0, r1, uk + row2 * 128 + ((sg2 ^ (row2 & 7)) << 4));
                bT[2][0] = r0; bT[2][1] = r1;
            }
#pragma unroll
            for (int mi = 0; mi < 3; mi++)
#pragma unroll
                for (int ni = 0; ni < 3; ni++)
                    mma_f16(acc[mi][ni], aT[mi][0], aT[mi][1], aT[mi][2], aT[mi][3],
                            bT[ni][0], bT[ni][1]);
        }
        __syncthreads();
        if (c + 2 < 4) attn_load_qk(sb, st, c + 2, Q, sq, K, sk, b, h, Lq, Lk, tid);
    }

#pragma unroll
    for (int mi = 0; mi < 3; mi++) {
        const int q0 = wm * 48 + mi * 16 + qr;
        const int q1 = q0 + 8;
        const int qok0 = (q0 < Lq) ? qm[b * Lq + q0] : 0;
        const int qok1 = (q1 < Lq) ? qm[b * Lq + q1] : 0;
#pragma unroll
        for (int ni = 0; ni < 3; ni++) {
            const int c0 = wn * 24 + ni * 8 + qc * 2;
            const int c1 = c0 + 1;
            const int k0ok = (km[b * Lk + c0] != 0);
            const int k1ok = (c1 < Lk) ? (km[b * Lk + c1] != 0) : 0;
            if (q0 < Lq) {
                if (c0 < Lk) Ss[q0 * 97 + c0] = (qok0 && k0ok) ? acc[mi][ni][0] * 0.0625f : NEGF;
                if (c1 < Lk) Ss[q0 * 97 + c1] = (qok0 && k1ok) ? acc[mi][ni][1] * 0.0625f : NEGF;
            }
            if (q1 < Lq) {
                if (c0 < Lk) Ss[q1 * 97 + c0] = (qok1 && k0ok) ? acc[mi][ni][2] * 0.0625f : NEGF;
                if (c1 < Lk) Ss[q1 * 97 + c1] = (qok1 && k1ok) ? acc[mi][ni][3] * 0.0625f : NEGF;
            }
        }
    }
    __syncthreads();

    // preload V chunks 0/1
    const int NCv = Lk >> 5;
    {
#pragma unroll
        for (int j = 0; j < 4; j++) {
            const int idx = tid + 256 * j;
            const int kr = idx >> 5, s2 = idx & 31;
            cp16(uV + kr * 512 + (((s2 ^ (kr & 7)) << 4)),
                 V + (size_t)(b * Lk + kr) * sv + h * DHv + s2 * 8);
        }
        CP_COMMIT();
        if (NCv > 1) {
#pragma unroll
            for (int j = 0; j < 4; j++) {
                const int idx = tid + 256 * j;
                const int kr = idx >> 5, s2 = idx & 31;
                cp16(uV + 16384u + kr * 512 + (((s2 ^ (kr & 7)) << 4)),
                     V + (size_t)(b * Lk + 32 + kr) * sv + h * DHv + s2 * 8);
            }
            CP_COMMIT();
        }
    }

    // phase 2: softmax -> P fp16
    {
        const int w = tid >> 5, l = tid & 31;
        for (int r = w; r < Lq; r += 8) {
            float* s = Ss + r * 97;
            float v0 = (l      < Lk) ? s[l]      : -3.4e38f;
            float v1 = (l + 32 < Lk) ? s[l + 32] : -3.4e38f;
            float v2 = (l + 64 < Lk) ? s[l + 64] : -3.4e38f;

            float mx = fmaxf(v0, fmaxf(v1, v2));
#pragma unroll
            for (int o = 16; o; o >>= 1) mx = fmaxf(mx, __shfl_xor_sync(0xffffffffu, mx, o));

            float e0 = (l      < Lk && v0 != NEGF) ? __expf(v0 - mx) : 0.0f;
            float e1 = (l + 32 < Lk && v1 != NEGF) ? __expf(v1 - mx) : 0.0f;
            float e2 = (l + 64 < Lk && v2 != NEGF) ? __expf(v2 - mx) : 0.0f;

            float sum = e0 + e1 + e2;
#pragma unroll
            for (int o = 16; o; o >>= 1) sum += __shfl_xor_sync(0xffffffffu, sum, o);

            const float inv = (sum > 0.0f) ? (1.0f / sum) : 0.0f;
            if (l      < Lk) P[r * 104 + l]      = __float2half(e0 * inv);
            if (l + 32 < Lk) P[r * 104 + l + 32] = __float2half(e1 * inv);
            if (l + 64 < Lk) P[r * 104 + l + 64] = __float2half(e2 * inv);
        }
    }
    __syncthreads();

    // phase 3: AO = P @ V
    float av[3][8][4];
#pragma unroll
    for (int mi = 0; mi < 3; mi++)
#pragma unroll
        for (int nt = 0; nt < 8; nt++)
#pragma unroll
            for (int r = 0; r < 4; r++) av[mi][nt][r] = 0.0f;

    for (int ci = 0; ci < NCv; ci++) {
        const int st = ci & 1;
        if (ci < NCv - 1) CP_WAIT1(); else CP_WAIT0();
        __syncthreads();

        const uint32_t uVs = uV + (uint32_t)st * 16384u;
        const int kk = ci * 32;

#pragma unroll
        for (int ks = 0; ks < 2; ks++) {
            const int k0 = kk + ks * 16;
            uint32_t aP[3][4];
#pragma unroll
            for (int mi = 0; mi < 3; mi++) {
                const int row = wm * 48 + mi * 16 + lane15;
                ldsm4(aP[mi][0], aP[mi][1], aP[mi][2], aP[mi][3],
                      uP + row * 208 + k0 * 2 + hi * 16);
            }
            uint32_t bV[8][2];
#pragma unroll
            for (int t2 = 0; t2 < 4; t2++) {
                const int n0 = wn * 64 + t2 * 16;
                const int kL = ks * 16 + ((lane >> 3) & 1) * 8 + (lane & 7);
                const int sgv = (n0 >> 3) + (lane >> 4);
                uint32_t r0, r1, r2, r3;
                ldsm4t(r0, r1, r2, r3,
                       uVs + kL * 512 + ((sgv ^ (kL & 7)) << 4));
                bV[2 * t2][0]     = r0; bV[2 * t2][1]     = r1;
                bV[2 * t2 + 1][0] = r2; bV[2 * t2 + 1][1] = r3;
            }
#pragma unroll
            for (int mi = 0; mi < 3; mi++)
#pragma unroll
                for (int nt = 0; nt < 8; nt++)
                    mma_f16(av[mi][nt], aP[mi][0], aP[mi][1], aP[mi][2], aP[mi][3],
                            bV[nt][0], bV[nt][1]);
        }
        __syncthreads();
        if (ci + 2 < NCv) {
            const int kk2 = (ci + 2) * 32;
#pragma unroll
            for (int j = 0; j < 4; j++) {
                const int idx = tid + 256 * j;
                const int kr = idx >> 5, s2 = idx & 31;
                cp16(uV + (uint32_t)st * 16384u + kr * 512 + (((s2 ^ (kr & 7)) << 4)),
                     V + (size_t)(b * Lk + kk2 + kr) * sv + h * DHv + s2 * 8);
            }
            CP_COMMIT();
        }
    }

#pragma unroll
    for (int mi = 0; mi < 3; mi++) {
        const int q0 = wm * 48 + mi * 16 + qr;
        const int q1 = q0 + 8;
#pragma unroll
        for (int nt = 0; nt < 8; nt++) {
            const int col = wn * 64 + nt * 8 + qc * 2;
            if (q0 < Lq) {
                __half2 hv = __floats2half2_rn(av[mi][nt][0], av[mi][nt][1]);
                *(__half2*)(AO + (size_t)(b * Lq + q0) * Dv + h * DHv + col) = hv;
            }
            if (q1 < Lq) {
                __half2 hv = __floats2half2_rn(av[mi][nt][2], av[mi][nt][3]);
                *(__half2*)(AO + (size_t)(b * Lq + q1) * Dv + h * DHv + col) = hv;
            }
        }
    }
}

// ---------------------------------------------------------------------------
// LayerNorm over fp16 input; fp32 out and/or fp16 out
// ---------------------------------------------------------------------------
__global__ void __launch_bounds__(256)
ln_kernel(const __half* __restrict__ X, const float* __restrict__ g,
          const float* __restrict__ b, float* __restrict__ Y,
          __half* __restrict__ Y16)
{
    const int row = blockIdx.x;
    const int t   = threadIdx.x;
    const uint2 u = ((const uint2*)(X + (size_t)row * Dv))[t];
    const float2 f0 = __half22float2(*(const __half2*)&u.x);
    const float2 f1 = __half22float2(*(const __half2*)&u.y);
    const float vx = f0.x, vy = f0.y, vz = f1.x, vw = f1.y;

    float s  = vx + vy + vz + vw;
    float ss = vx * vx + vy * vy + vz * vz + vw * vw;

    __shared__ float shs[8], shq[8];
#pragma unroll
    for (int o = 16; o; o >>= 1) {
        s  += __shfl_xor_sync(0xffffffffu, s,  o);
        ss += __shfl_xor_sync(0xffffffffu, ss, o);
    }
    const int w = t >> 5, l = t & 31;
    if (l == 0) { shs[w] = s; shq[w] = ss; }
    __syncthreads();
    float m = 0.0f, q = 0.0f;
#pragma unroll
    for (int i = 0; i < 8; i++) { m += shs[i]; q += shq[i]; }
    m *= (1.0f / Dv);
    q  = q * (1.0f / Dv) - m * m;
    const float r = rsqrtf(q + 1e-3f);

    const float4 gv = ((const float4*)g)[t];
    const float4 bv = ((const float4*)b)[t];
    float4 o;
    o.x = (vx - m) * r * gv.x + bv.x;
    o.y = (vy - m) * r * gv.y + bv.y;
    o.z = (vz - m) * r * gv.z + bv.z;
    o.w = (vw - m) * r * gv.w + bv.w;
    if (Y) ((float4*)(Y + (size_t)row * Dv))[t] = o;
    if (Y16) {
        __half2 h0 = __floats2half2_rn(o.x, o.y);
        __half2 h1 = __floats2half2_rn(o.z, o.w);
        uint2 uo;
        uo.x = *(uint32_t*)&h0;
        uo.y = *(uint32_t*)&h1;
        ((uint2*)(Y16 + (size_t)row * Dv))[t] = uo;
    }
}

// ---------------------------------------------------------------------------
// Host orchestration
// ---------------------------------------------------------------------------
static inline void gemm(cudaStream_t st, const __half* A, int lda, const __half* Wt,
                        const float* bias, float* C, __half* C16,
                        int M, int N, int K)
{
    dim3 grid(N / 128, M / 128);
    hgemm_kernel<<<grid, 256, SMEM_BYTES, st>>>(A, lda, Wt, bias, C, C16, M, N, K);
}

extern "C" void kernel_launch(void* const* d_in, const int* in_sizes, int n_in,
                              void* d_out, int out_size)
{
    const float* text_emb  = (const float*)d_in[0];
    const float* image_emb = (const float*)d_in[1];
    const int*   text_mask  = (const int*)d_in[2];
    const int*   image_mask = (const int*)d_in[3];
    const float* W_tp = (const float*)d_in[4];
    const float* b_tp = (const float*)d_in[5];
    const float* W_ip = (const float*)d_in[6];
    const float* b_ip = (const float*)d_in[7];
    const float* ta_Wq = (const float*)d_in[8];
    const float* ta_Wk = (const float*)d_in[9];
    const float* ta_Wv = (const float*)d_in[10];
    const float* ta_Wo = (const float*)d_in[11];
    const float* ia_Wq = (const float*)d_in[12];
    const float* ia_Wk = (const float*)d_in[13];
    const float* ia_Wv = (const float*)d_in[14];
    const float* ia_Wo = (const float*)d_in[15];
    const float* ts_Wq = (const float*)d_in[16];
    const float* ts_Wk = (const float*)d_in[17];
    const float* ts_Wv = (const float*)d_in[18];
    const float* ts_Wo = (const float*)d_in[19];
    const float* is_Wq = (const float*)d_in[20];
    const float* is_Wk = (const float*)d_in[21];
    const float* is_Wv = (const float*)d_in[22];
    const float* is_Wo = (const float*)d_in[23];
    const float* ln_ta_g = (const float*)d_in[24];
    const float* ln_ta_b = (const float*)d_in[25];
    const float* ln_ia_g = (const float*)d_in[26];
    const float* ln_ia_b = (const float*)d_in[27];
    const float* ln_ts_g = (const float*)d_in[28];
    const float* ln_ts_b = (const float*)d_in[29];
    const float* ln_is_g = (const float*)d_in[30];
    const float* ln_is_b = (const float*)d_in[31];

    float* out_text = (float*)d_out;
    float* out_img  = (float*)d_out + (size_t)Bv * LIv * Dv;

    __half *tE16, *iE16, *Wh, *Pt16, *PairT, *VT, *PiVI, *PairI;
    __half *AOT, *XT, *QKVT, *CTh, *AOI, *XI, *QKVI, *CIh;
    float *bPI;
    cudaGetSymbolAddress((void**)&tE16,   g_tE16);
    cudaGetSymbolAddress((void**)&iE16,   g_iE16);
    cudaGetSymbolAddress((void**)&Wh,     g_Wh);
    cudaGetSymbolAddress((void**)&Pt16,   g_Pt16);
    cudaGetSymbolAddress((void**)&PairT,  g_PairT);
    cudaGetSymbolAddress((void**)&VT,     g_VT);
    cudaGetSymbolAddress((void**)&PiVI,   g_PiVI);
    cudaGetSymbolAddress((void**)&PairI,  g_PairI);
    cudaGetSymbolAddress((void**)&AOT,    g_AOT);
    cudaGetSymbolAddress((void**)&XT,     g_XT);
    cudaGetSymbolAddress((void**)&QKVT,   g_QKVT);
    cudaGetSymbolAddress((void**)&CTh,    g_CTh);
    cudaGetSymbolAddress((void**)&AOI,    g_AOI);
    cudaGetSymbolAddress((void**)&XI,     g_XI);
    cudaGetSymbolAddress((void**)&QKVI,   g_QKVI);
    cudaGetSymbolAddress((void**)&CIh,    g_CIh);
    cudaGetSymbolAddress((void**)&bPI,    g_bPI);

    cudaFuncSetAttribute(hgemm_kernel,
                         cudaFuncAttributeMaxDynamicSharedMemorySize, SMEM_BYTES);
    cudaFuncSetAttribute(attn_mma_kernel,
                         cudaFuncAttributeMaxDynamicSharedMemorySize, ATTN_SMEM2);

    static cudaStream_t s1 = nullptr;
    static cudaEvent_t evFork = nullptr, ev2 = nullptr, ev2t = nullptr,
                       evW0 = nullptr, evA = nullptr, evB = nullptr,
                       evJoin = nullptr;
    if (!s1) {
        cudaStreamCreateWithFlags(&s1, cudaStreamNonBlocking);
        cudaEventCreateWithFlags(&evFork, cudaEventDisableTiming);
        cudaEventCreateWithFlags(&ev2, cudaEventDisableTiming);
        cudaEventCreateWithFlags(&ev2t, cudaEventDisableTiming);
        cudaEventCreateWithFlags(&evW0, cudaEventDisableTiming);
        cudaEventCreateWithFlags(&evA, cudaEventDisableTiming);
        cudaEventCreateWithFlags(&evB, cudaEventDisableTiming);
        cudaEventCreateWithFlags(&evJoin, cudaEventDisableTiming);
    }
    cudaStream_t s0 = (cudaStream_t)0;

    // Wh slot map (1M-half slots):
    //  0    W_tp^T
    //  1-2  pairPtW = [ta_Wk^T ; ia_Wq^T]
    //  3    ta_Wv^T
    //  4-5  pairPiW = [ta_Wq^T ; ia_Wk^T]
    //  6-9  WiVI    = [W_ip^T(2) ; ia_Wv^T(2)]   ([2048,2048])
    // 10    ta_Wo^T   11 ia_Wo^T
    // 12-14 ts QKV^T  15 ts_Wo^T
    // 16-18 is QKV^T  19 is_Wo^T
    #define WH(i)  (Wh + ((size_t)(i) << 20))

    // capture-legal fork
    cudaEventRecord(evFork, s0);
    cudaStreamWaitEvent(s1, evFork, 0);

    // ---- s1 weight prep, need-ordered ----
    // batch A: what the s0 Pt-chain needs (W_tp, pairPt) + ta_Wv for s1's VT
    SrcArr4 sa;
    sa.p[0] = W_tp; sa.p[1] = ta_Wk; sa.p[2] = ia_Wq; sa.p[3] = ta_Wv;
    transpose_kernel<SrcArr4><<<dim3(32, 32, 4), dim3(32, 8), 0, s1>>>(sa, Wh, 1024, 1 << 20);
    cudaEventRecord(evW0, s1);

    // batch B: Pi-chain weights
    SrcArr2 sb1;
    sb1.p[0] = ta_Wq; sb1.p[1] = ia_Wk;
    transpose_kernel<SrcArr2><<<dim3(32, 32, 2), dim3(32, 8), 0, s1>>>(sb1, WH(4), 1024, 1 << 20);
    SrcArr2 sb2;
    sb2.p[0] = W_ip; sb2.p[1] = ia_Wv;
    transpose_kernel<SrcArr2><<<dim3(32, 64, 2), dim3(32, 8), 0, s1>>>(sb2, WH(6), 2048, 1 << 21);
    bias_pad_kernel<<<8, 256, 0, s1>>>(b_ip, bPI);

    // batch C: branch weights (10 slabs) -- ordered before evB on s1
    SrcArr10 sc;
    sc.p[0] = ta_Wo; sc.p[1] = ia_Wo;
    sc.p[2] = ts_Wq; sc.p[3] = ts_Wk; sc.p[4] = ts_Wv; sc.p[5] = ts_Wo;
    sc.p[6] = is_Wq; sc.p[7] = is_Wk; sc.p[8] = is_Wv; sc.p[9] = is_Wo;
    transpose_kernel<SrcArr10><<<dim3(32, 32, 10), dim3(32, 8), 0, s1>>>(sc, WH(10), 1024, 1 << 20);

    // ---- s0: embedding fp16 (image FIRST -- s1's Pi chain needs only iE16) ----
    {
        const int n4i = Bv * LIv * DIv / 4;
        f2h_kernel<<<n4i / 256, 256, 0, s0>>>((const float4*)image_emb, (uint2*)iE16, n4i);
        cudaEventRecord(ev2, s0);         // image embedding ready
        const int n4t = Bv * LTv * DTv / 4;
        f2h_kernel<<<n4t / 256, 256, 0, s0>>>((const float4*)text_emb, (uint2*)tE16, n4t);
        cudaEventRecord(ev2t, s0);        // text embedding ready
    }

    const __half* tta_Wo  = WH(10);
    const __half* tia_Wo  = WH(11);
    const __half* tts_QKV = WH(12);
    const __half* tts_Wo  = WH(15);
    const __half* tis_QKV = WH(16);
    const __half* tis_Wo  = WH(19);

    const int Mt = Bv * LTv;   // 12288
    const int Mi = Bv * LIv;   // 8192

    // ---- s0: Pt chain (needs batch A) : 12.9 + 25.8 G ----
    cudaStreamWaitEvent(s0, evW0, 0);
    gemm(s0, tE16, 1024, WH(0), b_tp, nullptr, Pt16, Mt, 1024, 1024);
    gemm(s0, Pt16, 1024, WH(1), nullptr, nullptr, PairT, Mt, 2048, 1024);  // [KT|QI]
    cudaEventRecord(evA, s0);

    // ---- s1: Pi chain + VT : 34.4 + 17.2 + 12.9 G ----
    cudaStreamWaitEvent(s1, ev2, 0);
    gemm(s1, iE16, 2048, WH(6), bPI, nullptr, PiVI, Mi, 2048, 2048);       // [Pi|VI]
    gemm(s1, PiVI, 2048, WH(4), nullptr, nullptr, PairI, Mi, 2048, 1024);  // [QT|KI]
    cudaEventRecord(evB, s1);
    cudaStreamWaitEvent(s1, ev2t, 0);
    gemm(s1, tE16, 1024, WH(3), nullptr, nullptr, VT, Mt, 1024, 1024);     // VT

    // === branch I (image_att -> out_img) on s0 : 64.5 G ===
    cudaStreamWaitEvent(s0, evB, 0);
    attn_mma_kernel<<<BHv, 256, ATTN_SMEM2, s0>>>(PairT + 1024, 2048, PairI + 1024, 2048,
                                                  PiVI + 1024, 2048, AOI,
                                                  text_mask, image_mask, LTv, LIv);
    gemm(s0, AOI, 1024, tia_Wo, nullptr, nullptr, CIh, Mt, 1024, 1024);
    ln_kernel<<<Mt, 256, 0, s0>>>(CIh, ln_ia_g, ln_ia_b, nullptr, XI);
    gemm(s0, XI, 1024, tis_QKV, nullptr, nullptr, QKVI, Mt, 3072, 1024);
    attn_mma_kernel<<<BHv, 256, ATTN_SMEM2, s0>>>(QKVI, 3072, QKVI + 1024, 3072,
                                                  QKVI + 2048, 3072, AOI,
                                                  text_mask, text_mask, LTv, LTv);
    gemm(s0, AOI, 1024, tis_Wo, nullptr, nullptr, CIh, Mt, 1024, 1024);
    ln_kernel<<<Mt, 256, 0, s0>>>(CIh, ln_is_g, ln_is_b, out_img, nullptr);

    // === branch T (text_att -> out_text) on s1 : 43 G ===
    cudaStreamWaitEvent(s1, evA, 0);
    attn_mma_kernel<<<BHv, 256, ATTN_SMEM2, s1>>>(PairI, 2048, PairT, 2048,
                                                  VT, 1024, AOT,
                                                  image_mask, text_mask, LIv, LTv);
    gemm(s1, AOT, 1024, tta_Wo, nullptr, nullptr, CTh, Mi, 1024, 1024);
    ln_kernel<<<Mi, 256, 0, s1>>>(CTh, ln_ta_g, ln_ta_b, nullptr, XT);
    gemm(s1, XT, 1024, tts_QKV, nullptr, nullptr, QKVT, Mi, 3072, 1024);
    attn_mma_kernel<<<BHv, 256, ATTN_SMEM2, s1>>>(QKVT, 3072, QKVT + 1024, 3072,
                                                  QKVT + 2048, 3072, AOT,
                                                  image_mask, image_mask, LIv, LIv);
    gemm(s1, AOT, 1024, tts_Wo, nullptr, nullptr, CTh, Mi, 1024, 1024);
    ln_kernel<<<Mi, 256, 0, s1>>>(CTh, ln_ts_g, ln_ts_b, out_text, nullptr);
    cudaEventRecord(evJoin, s1);

    // join
    cudaStreamWaitEvent(s0, evJoin, 0);
}

// round 12
// speedup vs baseline: 1.0331x; 1.0331x over previous
#include <cuda_runtime.h>
#include <cuda_fp16.h>
#include <cstdint>

// ---------------------------------------------------------------------------
// Problem dims
// ---------------------------------------------------------------------------
#define Bv   128
#define LTv  96
#define LIv  64
#define Dv   1024
#define Hv   4
#define DHv  256
#define DTv  1024
#define DIv  2048
#define BHv  (Bv * Hv)    // 512

#define NEGF (-2147483648.0f)   // -2^31

// ---------------------------------------------------------------------------
// Scratch buffers
// ---------------------------------------------------------------------------
static __device__ __half g_tE16[(size_t)Bv * LTv * DTv];
static __device__ __half g_iE16[(size_t)Bv * LIv * DIv];
static __device__ __half g_PairVT[(size_t)Bv * LTv * 3072];  // tE @ [Wc | ta_Wv] = [KT | QI | VT]
static __device__ __half g_PiVI[(size_t)Bv * LIv * 2048];    // iE @ [W_ip | ia_Wv] = [Pi | VI]
static __device__ __half g_PairI[(size_t)Bv * LIv * 2048];   // Pi @ [ta_Wq | ia_Wk] = [QT | KI]
// branch T (text_att -> out_text), Mi rows
static __device__ __half g_AOT[(size_t)Bv * LIv * Dv];
static __device__ __half g_XT[(size_t)Bv * LIv * Dv];
static __device__ __half g_QKVT[(size_t)Bv * LIv * Dv * 3];
static __device__ __half g_CTh[(size_t)Bv * LIv * Dv];
// branch I (image_att -> out_img), Mt rows
static __device__ __half g_AOI[(size_t)Bv * LTv * Dv];
static __device__ __half g_XI[(size_t)Bv * LTv * Dv];
static __device__ __half g_QKVI[(size_t)Bv * LTv * Dv * 3];
static __device__ __half g_CIh[(size_t)Bv * LTv * Dv];
// weight arena: 22 x 1M-half slots (slot map in kernel_launch)
static __device__ __half g_Wh[(size_t)22 * 1024 * 1024];
// composed / padded biases
static __device__ float g_bcT[3072];
static __device__ float g_bPI[2048];

// ---------------------------------------------------------------------------
// PTX helpers
// ---------------------------------------------------------------------------
__device__ __forceinline__ uint32_t smem_u32(const void* p) {
    uint32_t a;
    asm("{ .reg .u64 t; cvta.to.shared.u64 t, %1; cvt.u32.u64 %0, t; }" : "=r"(a) : "l"(p));
    return a;
}
#define CP_COMMIT() asm volatile("cp.async.commit_group;" ::: "memory")
#define CP_WAIT1()  asm volatile("cp.async.wait_group 1;" ::: "memory")
#define CP_WAIT0()  asm volatile("cp.async.wait_group 0;" ::: "memory")

__device__ __forceinline__ void cp16(uint32_t dst, const void* src) {
    asm volatile("cp.async.cg.shared.global [%0], [%1], 16;" :: "r"(dst), "l"(src));
}
__device__ __forceinline__ void cp16z(uint32_t dst, const void* src, int sz) {
    asm volatile("cp.async.cg.shared.global [%0], [%1], 16, %2;"
                 :: "r"(dst), "l"(src), "r"(sz));
}
__device__ __forceinline__ void ldsm4(uint32_t& r0, uint32_t& r1, uint32_t& r2,
                                      uint32_t& r3, uint32_t addr) {
    asm volatile("ldmatrix.sync.aligned.m8n8.x4.shared.b16 {%0,%1,%2,%3}, [%4];"
                 : "=r"(r0), "=r"(r1), "=r"(r2), "=r"(r3) : "r"(addr));
}
__device__ __forceinline__ void ldsm4t(uint32_t& r0, uint32_t& r1, uint32_t& r2,
                                       uint32_t& r3, uint32_t addr) {
    asm volatile("ldmatrix.sync.aligned.m8n8.x4.trans.shared.b16 {%0,%1,%2,%3}, [%4];"
                 : "=r"(r0), "=r"(r1), "=r"(r2), "=r"(r3) : "r"(addr));
}
__device__ __forceinline__ void ldsm2(uint32_t& r0, uint32_t& r1, uint32_t addr) {
    asm volatile("ldmatrix.sync.aligned.m8n8.x2.shared.b16 {%0,%1}, [%2];"
                 : "=r"(r0), "=r"(r1) : "r"(addr));
}
__device__ __forceinline__ void mma_f16(float* c, uint32_t a0, uint32_t a1,
                                        uint32_t a2, uint32_t a3,
                                        uint32_t b0, uint32_t b1) {
    asm volatile(
        "mma.sync.aligned.m16n8k16.row.col.f32.f16.f16.f32 "
        "{%0,%1,%2,%3}, {%4,%5,%6,%7}, {%8,%9}, {%0,%1,%2,%3};"
        : "+f"(c[0]), "+f"(c[1]), "+f"(c[2]), "+f"(c[3])
        : "r"(a0), "r"(a1), "r"(a2), "r"(a3), "r"(b0), "r"(b1));
}

// ---------------------------------------------------------------------------
// fp16 mma GEMM: C[M,N] = A16[M,K(lda)] @ W[K,N] (+bias fp32).
// CTA 128x128, 8 warps, warp tile 64x32, BK=64, 3-stage cp.async.
// ---------------------------------------------------------------------------
#define STAGE_BYTES 32768u
#define NSTAGE      3
#define SMEM_BYTES  (NSTAGE * STAGE_BYTES)

__device__ __forceinline__ void load_chunk_h(uint32_t sb, int s,
                                             const __half* __restrict__ A, int lda,
                                             const __half* __restrict__ Wt,
                                             int K, int kk, int bm, int bn, int tid)
{
    const uint32_t uA = sb + (uint32_t)s * STAGE_BYTES;
    const uint32_t uB = uA + 16384u;
#pragma unroll
    for (int j = 0; j < 4; j++) {
        int idx = tid + 256 * j;
        int row = idx >> 3, seg = idx & 7;
        cp16(uA + row * 128 + ((seg ^ (row & 7)) << 4),
             A + (size_t)(bm + row) * lda + kk + seg * 8);
    }
#pragma unroll
    for (int j = 0; j < 4; j++) {
        int idx = tid + 256 * j;
        int row = idx >> 3, seg = idx & 7;
        cp16(uB + row * 128 + ((seg ^ (row & 7)) << 4),
             Wt + (size_t)(bn + row) * K + kk + seg * 8);
    }
    CP_COMMIT();
}

__global__ void __launch_bounds__(256, 2)
hgemm_kernel(const __half* __restrict__ A, int lda,
             const __half* __restrict__ Wt,
             const float* __restrict__ bias, float* __restrict__ C,
             __half* __restrict__ C16, int M, int N, int K)
{
    extern __shared__ char smc[];
    const uint32_t sb = smem_u32(smc);
    const int tid  = threadIdx.x;
    const int lane = tid & 31;
    const int warp = tid >> 5;
    const int wm   = warp >> 2;
    const int wn   = warp & 3;
    const int bm   = blockIdx.y * 128;
    const int bn   = blockIdx.x * 128;

    const int lane15 = lane & 15;
    const int hi     = lane >> 4;

    int arow[4], brow[2];
#pragma unroll
    for (int mi = 0; mi < 4; mi++) arow[mi] = wm * 64 + mi * 16 + lane15;
#pragma unroll
    for (int nb = 0; nb < 2; nb++) brow[nb] = wn * 32 + nb * 16 + lane15;

    float acc[4][4][4];
#pragma unroll
    for (int mi = 0; mi < 4; mi++)
#pragma unroll
        for (int ni = 0; ni < 4; ni++)
#pragma unroll
            for (int r = 0; r < 4; r++) acc[mi][ni][r] = 0.0f;

    const int NC = K >> 6;
    load_chunk_h(sb, 0, A, lda, Wt, K, 0,  bm, bn, tid);
    load_chunk_h(sb, 1, A, lda, Wt, K, 64, bm, bn, tid);

    int sc = 0, sl = 2;
    for (int i = 0; i < NC; i++) {
        if (i < NC - 1) CP_WAIT1(); else CP_WAIT0();
        __syncthreads();

        if (i + 2 < NC) {
            load_chunk_h(sb, sl, A, lda, Wt, K, (i + 2) * 64, bm, bn, tid);
            if (++sl == NSTAGE) sl = 0;
        }

        const uint32_t uA = sb + (uint32_t)sc * STAGE_BYTES;
        const uint32_t uB = uA + 16384u;
        if (++sc == NSTAGE) sc = 0;

#pragma unroll
        for (int ks = 0; ks < 4; ks++) {
            const int sg = ks * 2 + hi;
            uint32_t bf[4][2];
#pragma unroll
            for (int nb = 0; nb < 2; nb++) {
                uint32_t r0, r1, r2, r3;
                ldsm4(r0, r1, r2, r3,
                      uB + brow[nb] * 128 + ((sg ^ (brow[nb] & 7)) << 4));
                bf[nb * 2][0]     = r0; bf[nb * 2][1]     = r2;
                bf[nb * 2 + 1][0] = r1; bf[nb * 2 + 1][1] = r3;
            }
#pragma unroll
            for (int mi = 0; mi < 4; mi++) {
                uint32_t a0, a1, a2, a3;
                ldsm4(a0, a1, a2, a3,
                      uA + arow[mi] * 128 + ((sg ^ (arow[mi] & 7)) << 4));
#pragma unroll
                for (int ni = 0; ni < 4; ni++)
                    mma_f16(acc[mi][ni], a0, a1, a2, a3, bf[ni][0], bf[ni][1]);
            }
        }
    }

    const int qr = lane >> 2, qc = lane & 3;
#pragma unroll
    for (int mi = 0; mi < 4; mi++) {
        const int row = bm + wm * 64 + mi * 16 + qr;
#pragma unroll
        for (int ni = 0; ni < 4; ni++) {
            const int col = bn + wn * 32 + ni * 8 + qc * 2;
            float2 v0 = make_float2(acc[mi][ni][0], acc[mi][ni][1]);
            float2 v1 = make_float2(acc[mi][ni][2], acc[mi][ni][3]);
            if (bias) {
                const float2 bz = *(const float2*)(bias + col);
                v0.x += bz.x; v0.y += bz.y;
                v1.x += bz.x; v1.y += bz.y;
            }
            if (C) {
                *(float2*)(C + (size_t)row * N + col)       = v0;
                *(float2*)(C + (size_t)(row + 8) * N + col) = v1;
            }
            if (C16) {
                __half2 h0 = __floats2half2_rn(v0.x, v0.y);
                __half2 h1 = __floats2half2_rn(v1.x, v1.y);
                *(__half2*)(C16 + (size_t)row * N + col)       = h0;
                *(__half2*)(C16 + (size_t)(row + 8) * N + col) = h1;
            }
        }
    }
}

// ---------------------------------------------------------------------------
// fp32 -> fp16 convert
// ---------------------------------------------------------------------------
__global__ void __launch_bounds__(256)
f2h_kernel(const float4* __restrict__ src, uint2* __restrict__ dst, int n4)
{
    const int i = blockIdx.x * 256 + threadIdx.x;
    if (i < n4) {
        float4 v = src[i];
        __half2 h0 = __floats2half2_rn(v.x, v.y);
        __half2 h1 = __floats2half2_rn(v.z, v.w);
        uint2 o;
        o.x = *(uint32_t*)&h0;
        o.y = *(uint32_t*)&h1;
        dst[i] = o;
    }
}

// ---------------------------------------------------------------------------
// Batched weight transpose + fp16: dst[n][k] = fp16(src[k][n]), src [K,1024]
// ---------------------------------------------------------------------------
struct SrcArr1 { const float* p[1]; };
struct SrcArr2 { const float* p[2]; };
struct SrcArr5 { const float* p[5]; };

template <typename SA>
__global__ void __launch_bounds__(256)
transpose_kernel(SA srcs, __half* __restrict__ dstbase, int K, size_t dst_stride)
{
    __shared__ float t[32][33];
    const float* src = srcs.p[blockIdx.z];
    __half* dst = dstbase + (size_t)blockIdx.z * dst_stride;
    const int n0 = blockIdx.x * 32, k0 = blockIdx.y * 32;
    const int tx = threadIdx.x, ty = threadIdx.y;
#pragma unroll
    for (int j = 0; j < 32; j += 8)
        t[ty + j][tx] = src[(size_t)(k0 + ty + j) * 1024 + n0 + tx];
    __syncthreads();
#pragma unroll
    for (int j = 0; j < 32; j += 8)
        dst[(size_t)(n0 + ty + j) * K + k0 + tx] = __float2half(t[tx][ty + j]);
}

// Composed text bias: bcT[n] = sum_d b[d]*Wp[d,n] (Wp = [W1|W2]) for n<2048; else 0
__global__ void __launch_bounds__(256)
bias_ct_kernel(const float* __restrict__ b, const float* __restrict__ W1,
               const float* __restrict__ W2, float* __restrict__ out)
{
    const int n = blockIdx.x * 256 + threadIdx.x;   // 0..3071
    float s = 0.0f;
    if (n < 2048) {
        const float* W = (n < 1024) ? (W1 + n) : (W2 + n - 1024);
        for (int d = 0; d < 1024; d++) s += b[d] * W[(size_t)d * 1024];
    }
    out[n] = s;
}

__global__ void __launch_bounds__(256)
bias_pad_kernel(const float* __restrict__ b, float* __restrict__ out)
{
    const int n = blockIdx.x * 256 + threadIdx.x;   // 0..2047
    out[n] = (n < 1024) ? b[n] : 0.0f;
}

// ---------------------------------------------------------------------------
// Tensor-core fused attention (unchanged -- known good).
// ---------------------------------------------------------------------------
#define ATTN_SMEM2 90496

__device__ __forceinline__ void attn_load_qk(uint32_t sb, int st, int c,
        const __half* __restrict__ Q, int sq, const __half* __restrict__ K, int sk,
        int b, int h, int Lq, int Lk, int tid)
{
    const uint32_t uq = sb + (uint32_t)st * 24576u;
    const uint32_t uk = uq + 12288u;
#pragma unroll
    for (int j = 0; j < 3; j++) {
        const int idx = tid + 256 * j;
        const int row = idx >> 3, seg = idx & 7;
        const uint32_t off = row * 128 + ((seg ^ (row & 7)) << 4);
        {
            const int rq = (row < Lq) ? row : 0;
            cp16z(uq + off, Q + (size_t)(b * Lq + rq) * sq + h * DHv + c * 64 + seg * 8,
                  (row < Lq) ? 16 : 0);
        }
        {
            const int rk = (row < Lk) ? row : 0;
            cp16z(uk + off, K + (size_t)(b * Lk + rk) * sk + h * DHv + c * 64 + seg * 8,
                  (row < Lk) ? 16 : 0);
        }
    }
    CP_COMMIT();
}

__global__ void __launch_bounds__(256)
attn_mma_kernel(const __half* __restrict__ Q, int sq,
                const __half* __restrict__ K, int sk,
                const __half* __restrict__ V, int sv,
                __half* __restrict__ AO,
                const int* __restrict__ qm, const int* __restrict__ km,
                int Lq, int Lk)
{
    extern __shared__ char smb[];
    const uint32_t sb = smem_u32(smb);
    float*  Ss = (float*)(smb + 53248);
    __half* P  = (__half*)smb;           // row stride 104 halves
    const uint32_t uP = sb;
    const uint32_t uV = sb + 20480u;

    const int bh = blockIdx.x;
    const int b  = bh >> 2;
    const int h  = bh & 3;
    const int tid  = threadIdx.x;
    const int lane = tid & 31;
    const int warp = tid >> 5;
    const int wm   = warp >> 2;
    const int wn   = warp & 3;
    const int lane15 = lane & 15;
    const int hi     = lane >> 4;
    const int qr = lane >> 2, qc = lane & 3;

    // phase 1: scores = QK^T
    float acc[3][3][4];
#pragma unroll
    for (int mi = 0; mi < 3; mi++)
#pragma unroll
        for (int ni = 0; ni < 3; ni++)
#pragma unroll
            for (int r = 0; r < 4; r++) acc[mi][ni][r] = 0.0f;

    attn_load_qk(sb, 0, 0, Q, sq, K, sk, b, h, Lq, Lk, tid);
    attn_load_qk(sb, 1, 1, Q, sq, K, sk, b, h, Lq, Lk, tid);

    for (int c = 0; c < 4; c++) {
        const int st = c & 1;
        if (c < 3) CP_WAIT1(); else CP_WAIT0();
        __syncthreads();

        const uint32_t uq = sb + (uint32_t)st * 24576u;
        const uint32_t uk = uq + 12288u;

#pragma unroll
        for (int ks = 0; ks < 4; ks++) {
            const int sg = ks * 2 + hi;
            uint32_t aT[3][4];
#pragma unroll
            for (int mi = 0; mi < 3; mi++) {
                const int row = wm * 48 + mi * 16 + lane15;
                ldsm4(aT[mi][0], aT[mi][1], aT[mi][2], aT[mi][3],
                      uq + row * 128 + ((sg ^ (row & 7)) << 4));
            }
            uint32_t bT[3][2];
            {
                const int row = wn * 24 + lane15;
                uint32_t r0, r1, r2, r3;
                ldsm4(r0, r1, r2, r3, uk + row * 128 + ((sg ^ (row & 7)) << 4));
                bT[0][0] = r0; bT[0][1] = r2;
                bT[1][0] = r1; bT[1][1] = r3;
            }
            {
                const int row2 = wn * 24 + 16 + (lane & 7);
                const int sg2  = ks * 2 + ((lane >> 3) & 1);
                uint32_t r0, r1;
                ldsm2(r0, r1, uk + row2 * 128 + ((sg2 ^ (row2 & 7)) << 4));
                bT[2][0] = r0; bT[2][1] = r1;
            }
#pragma unroll
            for (int mi = 0; mi < 3; mi++)
#pragma unroll
                for (int ni = 0; ni < 3; ni++)
                    mma_f16(acc[mi][ni], aT[mi][0], aT[mi][1], aT[mi][2], aT[mi][3],
                            bT[ni][0], bT[ni][1]);
        }
        __syncthreads();
        if (c + 2 < 4) attn_load_qk(sb, st, c + 2, Q, sq, K, sk, b, h, Lq, Lk, tid);
    }

#pragma unroll
    for (int mi = 0; mi < 3; mi++) {
        const int q0 = wm * 48 + mi * 16 + qr;
        const int q1 = q0 + 8;
        const int qok0 = (q0 < Lq) ? qm[b * Lq + q0] : 0;
        const int qok1 = (q1 < Lq) ? qm[b * Lq + q1] : 0;
#pragma unroll
        for (int ni = 0; ni < 3; ni++) {
            const int c0 = wn * 24 + ni * 8 + qc * 2;
            const int c1 = c0 + 1;
            const int k0ok = (km[b * Lk + c0] != 0);
            const int k1ok = (c1 < Lk) ? (km[b * Lk + c1] != 0) : 0;
            if (q0 < Lq) {
                if (c0 < Lk) Ss[q0 * 97 + c0] = (qok0 && k0ok) ? acc[mi][ni][0] * 0.0625f : NEGF;
                if (c1 < Lk) Ss[q0 * 97 + c1] = (qok0 && k1ok) ? acc[mi][ni][1] * 0.0625f : NEGF;
            }
            if (q1 < Lq) {
                if (c0 < Lk) Ss[q1 * 97 + c0] = (qok1 && k0ok) ? acc[mi][ni][2] * 0.0625f : NEGF;
                if (c1 < Lk) Ss[q1 * 97 + c1] = (qok1 && k1ok) ? acc[mi][ni][3] * 0.0625f : NEGF;
            }
        }
    }
    __syncthreads();

    // preload V chunks 0/1
    const int NCv = Lk >> 5;
    {
#pragma unroll
        for (int j = 0; j < 4; j++) {
            const int idx = tid + 256 * j;
            const int kr = idx >> 5, s2 = idx & 31;
            cp16(uV + kr * 512 + (((s2 ^ (kr & 7)) << 4)),
                 V + (size_t)(b * Lk + kr) * sv + h * DHv + s2 * 8);
        }
        CP_COMMIT();
        if (NCv > 1) {
#pragma unroll
            for (int j = 0; j < 4; j++) {
                const int idx = tid + 256 * j;
                const int kr = idx >> 5, s2 = idx & 31;
                cp16(uV + 16384u + kr * 512 + (((s2 ^ (kr & 7)) << 4)),
                     V + (size_t)(b * Lk + 32 + kr) * sv + h * DHv + s2 * 8);
            }
            CP_COMMIT();
        }
    }

    // phase 2: softmax -> P fp16
    {
        const int w = tid >> 5, l = tid & 31;
        for (int r = w; r < Lq; r += 8) {
            float* s = Ss + r * 97;
            float v0 = (l      < Lk) ? s[l]      : -3.4e38f;
            float v1 = (l + 32 < Lk) ? s[l + 32] : -3.4e38f;
            float v2 = (l + 64 < Lk) ? s[l + 64] : -3.4e38f;

            float mx = fmaxf(v0, fmaxf(v1, v2));
#pragma unroll
            for (int o = 16; o; o >>= 1) mx = fmaxf(mx, __shfl_xor_sync(0xffffffffu, mx, o));

            float e0 = (l      < Lk && v0 != NEGF) ? __expf(v0 - mx) : 0.0f;
            float e1 = (l + 32 < Lk && v1 != NEGF) ? __expf(v1 - mx) : 0.0f;
            float e2 = (l + 64 < Lk && v2 != NEGF) ? __expf(v2 - mx) : 0.0f;

            float sum = e0 + e1 + e2;
#pragma unroll
            for (int o = 16; o; o >>= 1) sum += __shfl_xor_sync(0xffffffffu, sum, o);

            const float inv = (sum > 0.0f) ? (1.0f / sum) : 0.0f;
            if (l      < Lk) P[r * 104 + l]      = __float2half(e0 * inv);
            if (l + 32 < Lk) P[r * 104 + l + 32] = __float2half(e1 * inv);
            if (l + 64 < Lk) P[r * 104 + l + 64] = __float2half(e2 * inv);
        }
    }
    __syncthreads();

    // phase 3: AO = P @ V
    float av[3][8][4];
#pragma unroll
    for (int mi = 0; mi < 3; mi++)
#pragma unroll
        for (int nt = 0; nt < 8; nt++)
#pragma unroll
            for (int r = 0; r < 4; r++) av[mi][nt][r] = 0.0f;

    for (int ci = 0; ci < NCv; ci++) {
        const int st = ci & 1;
        if (ci < NCv - 1) CP_WAIT1(); else CP_WAIT0();
        __syncthreads();

        const uint32_t uVs = uV + (uint32_t)st * 16384u;
        const int kk = ci * 32;

#pragma unroll
        for (int ks = 0; ks < 2; ks++) {
            const int k0 = kk + ks * 16;
            uint32_t aP[3][4];
#pragma unroll
            for (int mi = 0; mi < 3; mi++) {
                const int row = wm * 48 + mi * 16 + lane15;
                ldsm4(aP[mi][0], aP[mi][1], aP[mi][2], aP[mi][3],
                      uP + row * 208 + k0 * 2 + hi * 16);
            }
            uint32_t bV[8][2];
#pragma unroll
            for (int t2 = 0; t2 < 4; t2++) {
                const int n0 = wn * 64 + t2 * 16;
                const int kL = ks * 16 + ((lane >> 3) & 1) * 8 + (lane & 7);
                const int sgv = (n0 >> 3) + (lane >> 4);
                uint32_t r0, r1, r2, r3;
                ldsm4t(r0, r1, r2, r3,
                       uVs + kL * 512 + ((sgv ^ (kL & 7)) << 4));
                bV[2 * t2][0]     = r0; bV[2 * t2][1]     = r1;
                bV[2 * t2 + 1][0] = r2; bV[2 * t2 + 1][1] = r3;
            }
#pragma unroll
            for (int mi = 0; mi < 3; mi++)
#pragma unroll
                for (int nt = 0; nt < 8; nt++)
                    mma_f16(av[mi][nt], aP[mi][0], aP[mi][1], aP[mi][2], aP[mi][3],
                            bV[nt][0], bV[nt][1]);
        }
        __syncthreads();
        if (ci + 2 < NCv) {
            const int kk2 = (ci + 2) * 32;
#pragma unroll
            for (int j = 0; j < 4; j++) {
                const int idx = tid + 256 * j;
                const int kr = idx >> 5, s2 = idx & 31;
                cp16(uV + (uint32_t)st * 16384u + kr * 512 + (((s2 ^ (kr & 7)) << 4)),
                     V + (size_t)(b * Lk + kk2 + kr) * sv + h * DHv + s2 * 8);
            }
            CP_COMMIT();
        }
    }

#pragma unroll
    for (int mi = 0; mi < 3; mi++) {
        const int q0 = wm * 48 + mi * 16 + qr;
        const int q1 = q0 + 8;
#pragma unroll
        for (int nt = 0; nt < 8; nt++) {
            const int col = wn * 64 + nt * 8 + qc * 2;
            if (q0 < Lq) {
                __half2 hv = __floats2half2_rn(av[mi][nt][0], av[mi][nt][1]);
                *(__half2*)(AO + (size_t)(b * Lq + q0) * Dv + h * DHv + col) = hv;
            }
            if (q1 < Lq) {
                __half2 hv = __floats2half2_rn(av[mi][nt][2], av[mi][nt][3]);
                *(__half2*)(AO + (size_t)(b * Lq + q1) * Dv + h * DHv + col) = hv;
            }
        }
    }
}

// ---------------------------------------------------------------------------
// LayerNorm over fp16 input; fp32 out and/or fp16 out
// ---------------------------------------------------------------------------
__global__ void __launch_bounds__(256)
ln_kernel(const __half* __restrict__ X, const float* __restrict__ g,
          const float* __restrict__ b, float* __restrict__ Y,
          __half* __restrict__ Y16)
{
    const int row = blockIdx.x;
    const int t   = threadIdx.x;
    const uint2 u = ((const uint2*)(X + (size_t)row * Dv))[t];
    const float2 f0 = __half22float2(*(const __half2*)&u.x);
    const float2 f1 = __half22float2(*(const __half2*)&u.y);
    const float vx = f0.x, vy = f0.y, vz = f1.x, vw = f1.y;

    float s  = vx + vy + vz + vw;
    float ss = vx * vx + vy * vy + vz * vz + vw * vw;

    __shared__ float shs[8], shq[8];
#pragma unroll
    for (int o = 16; o; o >>= 1) {
        s  += __shfl_xor_sync(0xffffffffu, s,  o);
        ss += __shfl_xor_sync(0xffffffffu, ss, o);
    }
    const int w = t >> 5, l = t & 31;
    if (l == 0) { shs[w] = s; shq[w] = ss; }
    __syncthreads();
    float m = 0.0f, q = 0.0f;
#pragma unroll
    for (int i = 0; i < 8; i++) { m += shs[i]; q += shq[i]; }
    m *= (1.0f / Dv);
    q  = q * (1.0f / Dv) - m * m;
    const float r = rsqrtf(q + 1e-3f);

    const float4 gv = ((const float4*)g)[t];
    const float4 bv = ((const float4*)b)[t];
    float4 o;
    o.x = (vx - m) * r * gv.x + bv.x;
    o.y = (vy - m) * r * gv.y + bv.y;
    o.z = (vz - m) * r * gv.z + bv.z;
    o.w = (vw - m) * r * gv.w + bv.w;
    if (Y) ((float4*)(Y + (size_t)row * Dv))[t] = o;
    if (Y16) {
        __half2 h0 = __floats2half2_rn(o.x, o.y);
        __half2 h1 = __floats2half2_rn(o.z, o.w);
        uint2 uo;
        uo.x = *(uint32_t*)&h0;
        uo.y = *(uint32_t*)&h1;
        ((uint2*)(Y16 + (size_t)row * Dv))[t] = uo;
    }
}

// ---------------------------------------------------------------------------
// Host orchestration
// ---------------------------------------------------------------------------
static inline void gemm(cudaStream_t st, const __half* A, int lda, const __half* Wt,
                        const float* bias, float* C, __half* C16,
                        int M, int N, int K)
{
    dim3 grid(N / 128, M / 128);
    hgemm_kernel<<<grid, 256, SMEM_BYTES, st>>>(A, lda, Wt, bias, C, C16, M, N, K);
}

extern "C" void kernel_launch(void* const* d_in, const int* in_sizes, int n_in,
                              void* d_out, int out_size)
{
    const float* text_emb  = (const float*)d_in[0];
    const float* image_emb = (const float*)d_in[1];
    const int*   text_mask  = (const int*)d_in[2];
    const int*   image_mask = (const int*)d_in[3];
    const float* W_tp = (const float*)d_in[4];
    const float* b_tp = (const float*)d_in[5];
    const float* W_ip = (const float*)d_in[6];
    const float* b_ip = (const float*)d_in[7];
    const float* ta_Wq = (const float*)d_in[8];
    const float* ta_Wk = (const float*)d_in[9];
    const float* ta_Wv = (const float*)d_in[10];
    const float* ta_Wo = (const float*)d_in[11];
    const float* ia_Wq = (const float*)d_in[12];
    const float* ia_Wk = (const float*)d_in[13];
    const float* ia_Wv = (const float*)d_in[14];
    const float* ia_Wo = (const float*)d_in[15];
    const float* ts_Wq = (const float*)d_in[16];
    const float* ts_Wk = (const float*)d_in[17];
    const float* ts_Wv = (const float*)d_in[18];
    const float* ts_Wo = (const float*)d_in[19];
    const float* is_Wq = (const float*)d_in[20];
    const float* is_Wk = (const float*)d_in[21];
    const float* is_Wv = (const float*)d_in[22];
    const float* is_Wo = (const float*)d_in[23];
    const float* ln_ta_g = (const float*)d_in[24];
    const float* ln_ta_b = (const float*)d_in[25];
    const float* ln_ia_g = (const float*)d_in[26];
    const float* ln_ia_b = (const float*)d_in[27];
    const float* ln_ts_g = (const float*)d_in[28];
    const float* ln_ts_b = (const float*)d_in[29];
    const float* ln_is_g = (const float*)d_in[30];
    const float* ln_is_b = (const float*)d_in[31];

    float* out_text = (float*)d_out;
    float* out_img  = (float*)d_out + (size_t)Bv * LIv * Dv;

    __half *tE16, *iE16, *Wh, *PairVT, *PiVI, *PairI;
    __half *AOT, *XT, *QKVT, *CTh, *AOI, *XI, *QKVI, *CIh;
    float *bcT, *bPI;
    cudaGetSymbolAddress((void**)&tE16,   g_tE16);
    cudaGetSymbolAddress((void**)&iE16,   g_iE16);
    cudaGetSymbolAddress((void**)&Wh,     g_Wh);
    cudaGetSymbolAddress((void**)&PairVT, g_PairVT);
    cudaGetSymbolAddress((void**)&PiVI,   g_PiVI);
    cudaGetSymbolAddress((void**)&PairI,  g_PairI);
    cudaGetSymbolAddress((void**)&AOT,    g_AOT);
    cudaGetSymbolAddress((void**)&XT,     g_XT);
    cudaGetSymbolAddress((void**)&QKVT,   g_QKVT);
    cudaGetSymbolAddress((void**)&CTh,    g_CTh);
    cudaGetSymbolAddress((void**)&AOI,    g_AOI);
    cudaGetSymbolAddress((void**)&XI,     g_XI);
    cudaGetSymbolAddress((void**)&QKVI,   g_QKVI);
    cudaGetSymbolAddress((void**)&CIh,    g_CIh);
    cudaGetSymbolAddress((void**)&bcT,    g_bcT);
    cudaGetSymbolAddress((void**)&bPI,    g_bPI);

    cudaFuncSetAttribute(hgemm_kernel,
                         cudaFuncAttributeMaxDynamicSharedMemorySize, SMEM_BYTES);
    cudaFuncSetAttribute(attn_mma_kernel,
                         cudaFuncAttributeMaxDynamicSharedMemorySize, ATTN_SMEM2);

    static cudaStream_t s1 = nullptr;
    static cudaEvent_t evFork = nullptr, ev2 = nullptr, evA = nullptr,
                       evB = nullptr, evJoin = nullptr;
    if (!s1) {
        cudaStreamCreateWithFlags(&s1, cudaStreamNonBlocking);
        cudaEventCreateWithFlags(&evFork, cudaEventDisableTiming);
        cudaEventCreateWithFlags(&ev2, cudaEventDisableTiming);
        cudaEventCreateWithFlags(&evA, cudaEventDisableTiming);
        cudaEventCreateWithFlags(&evB, cudaEventDisableTiming);
        cudaEventCreateWithFlags(&evJoin, cudaEventDisableTiming);
    }
    cudaStream_t s0 = (cudaStream_t)0;

    // Wh slot map (1M-half slots):
    //  0    W_tp fp16 natural (f2h)         [dt, d]
    //  1-2  pairPtW = [ta_Wk^T ; ia_Wq^T]   [n, d]   (compose A)
    //  3-4  pairPiW = [ta_Wq^T ; ia_Wk^T]
    //  5-8  WiVI    = [W_ip^T(2) ; ia_Wv^T(2)]  ([2048, 2048])
    //  9    ia_Wo^T  10-12 is_QKV^T  13 is_Wo^T   (branch-I weights, s0)
    // 14    ta_Wo^T  15-17 ts_QKV^T  18 ts_Wo^T   (branch-T weights, s1)
    // 19-21 WcVT = [Wc^T (19-20) ; ta_Wv^T (21)]  ([3072, 1024], PairVT Wt)
    #define WH(i)  (Wh + ((size_t)(i) << 20))

    // capture-legal fork
    cudaEventRecord(evFork, s0);
    cudaStreamWaitEvent(s1, evFork, 0);

    const int Mt = Bv * LTv;   // 12288
    const int Mi = Bv * LIv;   // 8192

    // =========================== s0 prologue ===========================
    // embeddings (image first; s1 needs only iE16)
    {
        const int n4i = Bv * LIv * DIv / 4;
        f2h_kernel<<<n4i / 256, 256, 0, s0>>>((const float4*)image_emb, (uint2*)iE16, n4i);
        cudaEventRecord(ev2, s0);
        const int n4t = Bv * LTv * DTv / 4;
        f2h_kernel<<<n4t / 256, 256, 0, s0>>>((const float4*)text_emb, (uint2*)tE16, n4t);
    }
    // text-side weight compose (all in-stream on s0)
    f2h_kernel<<<1024, 256, 0, s0>>>((const float4*)W_tp, (uint2*)WH(0), 262144);
    {
        SrcArr2 sp; sp.p[0] = ta_Wk; sp.p[1] = ia_Wq;
        transpose_kernel<SrcArr2><<<dim3(32, 32, 2), dim3(32, 8), 0, s0>>>(sp, WH(1), 1024, 1 << 20);
        SrcArr1 sv; sv.p[0] = ta_Wv;
        transpose_kernel<SrcArr1><<<dim3(32, 32, 1), dim3(32, 8), 0, s0>>>(sv, WH(21), 1024, 0);
    }
    bias_ct_kernel<<<12, 256, 0, s0>>>(b_tp, ta_Wk, ia_Wq, bcT);
    // Wc^T[n, dt] = sum_d pairPtW[n, d] * W_tp[dt, d]
    gemm(s0, WH(1), 1024, WH(0), nullptr, nullptr, WH(19), 2048, 1024, 1024);
    // PairVT = tE16 @ [Wc | ta_Wv]  -> [KT | QI | VT]
    gemm(s0, tE16, 1024, WH(19), bcT, nullptr, PairVT, Mt, 3072, 1024);
    cudaEventRecord(evA, s0);
    // branch-I weights (consumed by s0 later, in-stream)
    {
        SrcArr5 sc1;
        sc1.p[0] = ia_Wo;
        sc1.p[1] = is_Wq; sc1.p[2] = is_Wk; sc1.p[3] = is_Wv; sc1.p[4] = is_Wo;
        transpose_kernel<SrcArr5><<<dim3(32, 32, 5), dim3(32, 8), 0, s0>>>(sc1, WH(9), 1024, 1 << 20);
    }

    // =========================== s1 prologue ===========================
    {
        SrcArr2 sw; sw.p[0] = W_ip; sw.p[1] = ia_Wv;
        transpose_kernel<SrcArr2><<<dim3(32, 64, 2), dim3(32, 8), 0, s1>>>(sw, WH(5), 2048, 1 << 21);
        SrcArr2 sp; sp.p[0] = ta_Wq; sp.p[1] = ia_Wk;
        transpose_kernel<SrcArr2><<<dim3(32, 32, 2), dim3(32, 8), 0, s1>>>(sp, WH(3), 1024, 1 << 20);
    }
    bias_pad_kernel<<<8, 256, 0, s1>>>(b_ip, bPI);
    cudaStreamWaitEvent(s1, ev2, 0);
    gemm(s1, iE16, 2048, WH(5), bPI, nullptr, PiVI, Mi, 2048, 2048);       // [Pi|VI]
    gemm(s1, PiVI, 2048, WH(3), nullptr, nullptr, PairI, Mi, 2048, 1024);  // [QT|KI]
    cudaEventRecord(evB, s1);
    // branch-T weights (consumed by s1 later, in-stream)
    {
        SrcArr5 sc2;
        sc2.p[0] = ta_Wo;
        sc2.p[1] = ts_Wq; sc2.p[2] = ts_Wk; sc2.p[3] = ts_Wv; sc2.p[4] = ts_Wo;
        transpose_kernel<SrcArr5><<<dim3(32, 32, 5), dim3(32, 8), 0, s1>>>(sc2, WH(14), 1024, 1 << 20);
    }

    const __half* tia_Wo  = WH(9);
    const __half* tis_QKV = WH(10);
    const __half* tis_Wo  = WH(13);
    const __half* tta_Wo  = WH(14);
    const __half* tts_QKV = WH(15);
    const __half* tts_Wo  = WH(18);

    // === branch I (image_att -> out_img) on s0 ===
    cudaStreamWaitEvent(s0, evB, 0);
    attn_mma_kernel<<<BHv, 256, ATTN_SMEM2, s0>>>(PairVT + 1024, 3072, PairI + 1024, 2048,
                                                  PiVI + 1024, 2048, AOI,
                                                  text_mask, image_mask, LTv, LIv);
    gemm(s0, AOI, 1024, tia_Wo, nullptr, nullptr, CIh, Mt, 1024, 1024);
    ln_kernel<<<Mt, 256, 0, s0>>>(CIh, ln_ia_g, ln_ia_b, nullptr, XI);
    gemm(s0, XI, 1024, tis_QKV, nullptr, nullptr, QKVI, Mt, 3072, 1024);
    attn_mma_kernel<<<BHv, 256, ATTN_SMEM2, s0>>>(QKVI, 3072, QKVI + 1024, 3072,
                                                  QKVI + 2048, 3072, AOI,
                                                  text_mask, text_mask, LTv, LTv);
    gemm(s0, AOI, 1024, tis_Wo, nullptr, nullptr, CIh, Mt, 1024, 1024);
    ln_kernel<<<Mt, 256, 0, s0>>>(CIh, ln_is_g, ln_is_b, out_img, nullptr);

    // === branch T (text_att -> out_text) on s1 ===
    cudaStreamWaitEvent(s1, evA, 0);
    attn_mma_kernel<<<BHv, 256, ATTN_SMEM2, s1>>>(PairI, 2048, PairVT, 3072,
                                                  PairVT + 2048, 3072, AOT,
                                                  image_mask, text_mask, LIv, LTv);
    gemm(s1, AOT, 1024, tta_Wo, nullptr, nullptr, CTh, Mi, 1024, 1024);
    ln_kernel<<<Mi, 256, 0, s1>>>(CTh, ln_ta_g, ln_ta_b, nullptr, XT);
    gemm(s1, XT, 1024, tts_QKV, nullptr, nullptr, QKVT, Mi, 3072, 1024);
    attn_mma_kernel<<<BHv, 256, ATTN_SMEM2, s1>>>(QKVT, 3072, QKVT + 1024, 3072,
                                                  QKVT + 2048, 3072, AOT,
                                                  image_mask, image_mask, LIv, LIv);
    gemm(s1, AOT, 1024, tts_Wo, nullptr, nullptr, CTh, Mi, 1024, 1024);
    ln_kernel<<<Mi, 256, 0, s1>>>(CTh, ln_ts_g, ln_ts_b, out_text, nullptr);
    cudaEventRecord(evJoin, s1);

    // join
    cudaStreamWaitEvent(s0, evJoin, 0);
}

// round 14
// speedup vs baseline: 1.1575x; 1.1204x over previous
#include <cuda_runtime.h>
#include <cuda_fp16.h>
#include <cstdint>

// ---------------------------------------------------------------------------
// Problem dims
// ---------------------------------------------------------------------------
#define Bv   128
#define LTv  96
#define LIv  64
#define Dv   1024
#define Hv   4
#define DHv  256
#define DTv  1024
#define DIv  2048
#define BHv  (Bv * Hv)    // 512

#define NEGF (-2147483648.0f)   // -2^31

// ---------------------------------------------------------------------------
// Scratch buffers
// ---------------------------------------------------------------------------
static __device__ __half g_tE16[(size_t)Bv * LTv * DTv];
static __device__ __half g_iE16[(size_t)Bv * LIv * DIv];
static __device__ __half g_PairVT[(size_t)Bv * LTv * 3072];  // tE @ [Wc | ta_Wv] = [KT | QI | VT]
static __device__ __half g_PiVI[(size_t)Bv * LIv * 2048];    // iE @ [W_ip | ia_Wv] = [Pi | VI]
static __device__ __half g_PairI[(size_t)Bv * LIv * 2048];   // Pi @ [ta_Wq | ia_Wk] = [QT | KI]
// branch T (text_att -> out_text), Mi rows
static __device__ __half g_AOT[(size_t)Bv * LIv * Dv];
static __device__ __half g_XT[(size_t)Bv * LIv * Dv];
static __device__ __half g_QKVT[(size_t)Bv * LIv * Dv * 3];
static __device__ __half g_CTh[(size_t)Bv * LIv * Dv];
// branch I (image_att -> out_img), Mt rows
static __device__ __half g_AOI[(size_t)Bv * LTv * Dv];
static __device__ __half g_XI[(size_t)Bv * LTv * Dv];
static __device__ __half g_QKVI[(size_t)Bv * LTv * Dv * 3];
static __device__ __half g_CIh[(size_t)Bv * LTv * Dv];
// weight arena: 22 x 1M-half slots (slot map in kernel_launch); all NATURAL [K,N]
static __device__ __half g_Wh[(size_t)22 * 1024 * 1024];
// composed / padded biases
static __device__ float g_bcT[3072];
static __device__ float g_bPI[2048];

// ---------------------------------------------------------------------------
// PTX helpers
// ---------------------------------------------------------------------------
__device__ __forceinline__ uint32_t smem_u32(const void* p) {
    uint32_t a;
    asm("{ .reg .u64 t; cvta.to.shared.u64 t, %1; cvt.u32.u64 %0, t; }" : "=r"(a) : "l"(p));
    return a;
}
#define CP_COMMIT() asm volatile("cp.async.commit_group;" ::: "memory")
#define CP_WAIT1()  asm volatile("cp.async.wait_group 1;" ::: "memory")
#define CP_WAIT0()  asm volatile("cp.async.wait_group 0;" ::: "memory")

__device__ __forceinline__ void cp16(uint32_t dst, const void* src) {
    asm volatile("cp.async.cg.shared.global [%0], [%1], 16;" :: "r"(dst), "l"(src));
}
__device__ __forceinline__ void cp16z(uint32_t dst, const void* src, int sz) {
    asm volatile("cp.async.cg.shared.global [%0], [%1], 16, %2;"
                 :: "r"(dst), "l"(src), "r"(sz));
}
__device__ __forceinline__ void ldsm4(uint32_t& r0, uint32_t& r1, uint32_t& r2,
                                      uint32_t& r3, uint32_t addr) {
    asm volatile("ldmatrix.sync.aligned.m8n8.x4.shared.b16 {%0,%1,%2,%3}, [%4];"
                 : "=r"(r0), "=r"(r1), "=r"(r2), "=r"(r3) : "r"(addr));
}
__device__ __forceinline__ void ldsm4t(uint32_t& r0, uint32_t& r1, uint32_t& r2,
                                       uint32_t& r3, uint32_t addr) {
    asm volatile("ldmatrix.sync.aligned.m8n8.x4.trans.shared.b16 {%0,%1,%2,%3}, [%4];"
                 : "=r"(r0), "=r"(r1), "=r"(r2), "=r"(r3) : "r"(addr));
}
__device__ __forceinline__ void ldsm2(uint32_t& r0, uint32_t& r1, uint32_t addr) {
    asm volatile("ldmatrix.sync.aligned.m8n8.x2.shared.b16 {%0,%1}, [%2];"
                 : "=r"(r0), "=r"(r1) : "r"(addr));
}
__device__ __forceinline__ void mma_f16(float* c, uint32_t a0, uint32_t a1,
                                        uint32_t a2, uint32_t a3,
                                        uint32_t b0, uint32_t b1) {
    asm volatile(
        "mma.sync.aligned.m16n8k16.row.col.f32.f16.f16.f32 "
        "{%0,%1,%2,%3}, {%4,%5,%6,%7}, {%8,%9}, {%0,%1,%2,%3};"
        : "+f"(c[0]), "+f"(c[1]), "+f"(c[2]), "+f"(c[3])
        : "r"(a0), "r"(a1), "r"(a2), "r"(a3), "r"(b0), "r"(b1));
}

// ---------------------------------------------------------------------------
// fp16 mma GEMM (NT): C16[M,N(ldc)] = A16[M,K(lda)] @ W[K,N(ldw)] (+bias fp32).
// W is NATURAL row-major [K, N] -- B fragments via ldmatrix.trans (same
// pattern as the verified attention phase-3 P@V path).
// CTA 128x128, 8 warps, warp tile 64x32, BK=64, 3-stage cp.async.
// ---------------------------------------------------------------------------
#define STAGE_BYTES 32768u
#define NSTAGE      3
#define SMEM_BYTES  (NSTAGE * STAGE_BYTES)

__device__ __forceinline__ void load_chunk_nt(uint32_t sb, int s,
                                              const __half* __restrict__ A, int lda,
                                              const __half* __restrict__ W, int ldw,
                                              int kk, int bm, int bn, int tid)
{
    const uint32_t uA = sb + (uint32_t)s * STAGE_BYTES;
    const uint32_t uB = uA + 16384u;
    // A: 128 rows x 128 B (64 fp16), K-contiguous
#pragma unroll
    for (int j = 0; j < 4; j++) {
        int idx = tid + 256 * j;
        int row = idx >> 3, seg = idx & 7;
        cp16(uA + row * 128 + ((seg ^ (row & 7)) << 4),
             A + (size_t)(bm + row) * lda + kk + seg * 8);
    }
    // B: 64 K-rows x 256 B (128 fp16 N-cols), natural layout
#pragma unroll
    for (int j = 0; j < 4; j++) {
        int idx = tid + 256 * j;
        int row = idx >> 4, seg = idx & 15;
        cp16(uB + row * 256 + ((seg ^ (row & 7)) << 4),
             W + (size_t)(kk + row) * ldw + bn + seg * 8);
    }
    CP_COMMIT();
}

__global__ void __launch_bounds__(256, 2)
hgemm_kernel(const __half* __restrict__ A, int lda,
             const __half* __restrict__ W, int ldw,
             const float* __restrict__ bias,
             __half* __restrict__ C16, int ldc,
             int M, int N, int K)
{
    extern __shared__ char smc[];
    const uint32_t sb = smem_u32(smc);
    const int tid  = threadIdx.x;
    const int lane = tid & 31;
    const int warp = tid >> 5;
    const int wm   = warp >> 2;
    const int wn   = warp & 3;
    const int bm   = blockIdx.y * 128;
    const int bn   = blockIdx.x * 128;

    const int lane15 = lane & 15;
    const int hi     = lane >> 4;

    int arow[4];
#pragma unroll
    for (int mi = 0; mi < 4; mi++) arow[mi] = wm * 64 + mi * 16 + lane15;

    float acc[4][4][4];
#pragma unroll
    for (int mi = 0; mi < 4; mi++)
#pragma unroll
        for (int ni = 0; ni < 4; ni++)
#pragma unroll
            for (int r = 0; r < 4; r++) acc[mi][ni][r] = 0.0f;

    const int NC = K >> 6;
    load_chunk_nt(sb, 0, A, lda, W, ldw, 0,  bm, bn, tid);
    load_chunk_nt(sb, 1, A, lda, W, ldw, 64, bm, bn, tid);

    int sc = 0, sl = 2;
    for (int i = 0; i < NC; i++) {
        if (i < NC - 1) CP_WAIT1(); else CP_WAIT0();
        __syncthreads();

        if (i + 2 < NC) {
            load_chunk_nt(sb, sl, A, lda, W, ldw, (i + 2) * 64, bm, bn, tid);
            if (++sl == NSTAGE) sl = 0;
        }

        const uint32_t uA = sb + (uint32_t)sc * STAGE_BYTES;
        const uint32_t uB = uA + 16384u;
        if (++sc == NSTAGE) sc = 0;

#pragma unroll
        for (int ks = 0; ks < 4; ks++) {
            const int sg = ks * 2 + hi;
            // B fragments via ldmatrix.trans on natural [K,N] tile
            uint32_t bf[4][2];
#pragma unroll
            for (int nb = 0; nb < 2; nb++) {
                const int n0  = wn * 32 + nb * 16;
                const int kL  = ks * 16 + ((lane >> 3) & 1) * 8 + (lane & 7);
                const int sgv = (n0 >> 3) + (lane >> 4);
                uint32_t r0, r1, r2, r3;
                ldsm4t(r0, r1, r2, r3,
                       uB + kL * 256 + ((sgv ^ (kL & 7)) << 4));
                bf[nb * 2][0]     = r0; bf[nb * 2][1]     = r1;
                bf[nb * 2 + 1][0] = r2; bf[nb * 2 + 1][1] = r3;
            }
#pragma unroll
            for (int mi = 0; mi < 4; mi++) {
                uint32_t a0, a1, a2, a3;
                ldsm4(a0, a1, a2, a3,
                      uA + arow[mi] * 128 + ((sg ^ (arow[mi] & 7)) << 4));
#pragma unroll
                for (int ni = 0; ni < 4; ni++)
                    mma_f16(acc[mi][ni], a0, a1, a2, a3, bf[ni][0], bf[ni][1]);
            }
        }
    }

    const int qr = lane >> 2, qc = lane & 3;
#pragma unroll
    for (int mi = 0; mi < 4; mi++) {
        const int row = bm + wm * 64 + mi * 16 + qr;
#pragma unroll
        for (int ni = 0; ni < 4; ni++) {
            const int col = bn + wn * 32 + ni * 8 + qc * 2;
            float2 v0 = make_float2(acc[mi][ni][0], acc[mi][ni][1]);
            float2 v1 = make_float2(acc[mi][ni][2], acc[mi][ni][3]);
            if (bias) {
                const float2 bz = *(const float2*)(bias + col);
                v0.x += bz.x; v0.y += bz.y;
                v1.x += bz.x; v1.y += bz.y;
            }
            __half2 h0 = __floats2half2_rn(v0.x, v0.y);
            __half2 h1 = __floats2half2_rn(v1.x, v1.y);
            *(__half2*)(C16 + (size_t)row * ldc + col)       = h0;
            *(__half2*)(C16 + (size_t)(row + 8) * ldc + col) = h1;
        }
    }
}

// ---------------------------------------------------------------------------
// fp32 -> fp16 convert (contiguous)
// ---------------------------------------------------------------------------
__global__ void __launch_bounds__(256)
f2h_kernel(const float4* __restrict__ src, uint2* __restrict__ dst, int n4)
{
    const int i = blockIdx.x * 256 + threadIdx.x;
    if (i < n4) {
        float4 v = src[i];
        __half2 h0 = __floats2half2_rn(v.x, v.y);
        __half2 h1 = __floats2half2_rn(v.z, v.w);
        uint2 o;
        o.x = *(uint32_t*)&h0;
        o.y = *(uint32_t*)&h1;
        dst[i] = o;
    }
}

// ---------------------------------------------------------------------------
// Strided batched fp32->fp16: srcs.p[z] is [K,1024] fp32; row r, cols 0..1023
// go to dst + z*zStride + r*dstStride.  grid (K, 1, nz), 256 threads/row.
// ---------------------------------------------------------------------------
struct SrcArr1 { const float* p[1]; };
struct SrcArr2 { const float* p[2]; };
struct SrcArr3 { const float* p[3]; };

template <typename SA>
__global__ void __launch_bounds__(256)
f2hs_kernel(SA srcs, __half* __restrict__ dst, size_t zStride, int dstStride)
{
    const int row = blockIdx.x;
    const int z   = blockIdx.z;
    const float4* src = (const float4*)(srcs.p[z] + (size_t)row * 1024);
    __half* d = dst + (size_t)z * zStride + (size_t)row * dstStride;
    const int t = threadIdx.x;
    float4 v = src[t];
    __half2 h0 = __floats2half2_rn(v.x, v.y);
    __half2 h1 = __floats2half2_rn(v.z, v.w);
    uint2 o;
    o.x = *(uint32_t*)&h0;
    o.y = *(uint32_t*)&h1;
    *(uint2*)(d + t * 4) = o;
}

// Composed text bias: bcT[n] = sum_d b[d]*Wp[d,n] (Wp = [W1|W2]) for n<2048; else 0
__global__ void __launch_bounds__(256)
bias_ct_kernel(const float* __restrict__ b, const float* __restrict__ W1,
               const float* __restrict__ W2, float* __restrict__ out)
{
    const int n = blockIdx.x * 256 + threadIdx.x;   // 0..3071
    float s = 0.0f;
    if (n < 2048) {
        const float* W = (n < 1024) ? (W1 + n) : (W2 + n - 1024);
        for (int d = 0; d < 1024; d++) s += b[d] * W[(size_t)d * 1024];
    }
    out[n] = s;
}

__global__ void __launch_bounds__(256)
bias_pad_kernel(const float* __restrict__ b, float* __restrict__ out)
{
    const int n = blockIdx.x * 256 + threadIdx.x;   // 0..2047
    out[n] = (n < 1024) ? b[n] : 0.0f;
}

// ---------------------------------------------------------------------------
// Tensor-core fused attention (unchanged -- known good).
// ---------------------------------------------------------------------------
#define ATTN_SMEM2 90496

__device__ __forceinline__ void attn_load_qk(uint32_t sb, int st, int c,
        const __half* __restrict__ Q, int sq, const __half* __restrict__ K, int sk,
        int b, int h, int Lq, int Lk, int tid)
{
    const uint32_t uq = sb + (uint32_t)st * 24576u;
    const uint32_t uk = uq + 12288u;
#pragma unroll
    for (int j = 0; j < 3; j++) {
        const int idx = tid + 256 * j;
        const int row = idx >> 3, seg = idx & 7;
        const uint32_t off = row * 128 + ((seg ^ (row & 7)) << 4);
        {
            const int rq = (row < Lq) ? row : 0;
            cp16z(uq + off, Q + (size_t)(b * Lq + rq) * sq + h * DHv + c * 64 + seg * 8,
                  (row < Lq) ? 16 : 0);
        }
        {
            const int rk = (row < Lk) ? row : 0;
            cp16z(uk + off, K + (size_t)(b * Lk + rk) * sk + h * DHv + c * 64 + seg * 8,
                  (row < Lk) ? 16 : 0);
        }
    }
    CP_COMMIT();
}

__global__ void __launch_bounds__(256)
attn_mma_kernel(const __half* __restrict__ Q, int sq,
                const __half* __restrict__ K, int sk,
                const __half* __restrict__ V, int sv,
                __half* __restrict__ AO,
                const int* __restrict__ qm, const int* __restrict__ km,
                int Lq, int Lk)
{
    extern __shared__ char smb[];
    const uint32_t sb = smem_u32(smb);
    float*  Ss = (float*)(smb + 53248);
    __half* P  = (__half*)smb;           // row stride 104 halves
    const uint32_t uP = sb;
    const uint32_t uV = sb + 20480u;

    const int bh = blockIdx.x;
    const int b  = bh >> 2;
    const int h  = bh & 3;
    const int tid  = threadIdx.x;
    const int lane = tid & 31;
    const int warp = tid >> 5;
    const int wm   = warp >> 2;
    const int wn   = warp & 3;
    const int lane15 = lane & 15;
    const int hi     = lane >> 4;
    const int qr = lane >> 2, qc = lane & 3;

    // phase 1: scores = QK^T
    float acc[3][3][4];
#pragma unroll
    for (int mi = 0; mi < 3; mi++)
#pragma unroll
        for (int ni = 0; ni < 3; ni++)
#pragma unroll
            for (int r = 0; r < 4; r++) acc[mi][ni][r] = 0.0f;

    attn_load_qk(sb, 0, 0, Q, sq, K, sk, b, h, Lq, Lk, tid);
    attn_load_qk(sb, 1, 1, Q, sq, K, sk, b, h, Lq, Lk, tid);

    for (int c = 0; c < 4; c++) {
        const int st = c & 1;
        if (c < 3) CP_WAIT1(); else CP_WAIT0();
        __syncthreads();

        const uint32_t uq = sb + (uint32_t)st * 24576u;
        const uint32_t uk = uq + 12288u;

#pragma unroll
        for (int ks = 0; ks < 4; ks++) {
            const int sg = ks * 2 + hi;
            uint32_t aT[3][4];
#pragma unroll
            for (int mi = 0; mi < 3; mi++) {
                const int row = wm * 48 + mi * 16 + lane15;
                ldsm4(aT[mi][0], aT[mi][1], aT[mi][2], aT[mi][3],
                      uq + row * 128 + ((sg ^ (row & 7)) << 4));
            }
            uint32_t bT[3][2];
            {
                const int row = wn * 24 + lane15;
                uint32_t r0, r1, r2, r3;
                ldsm4(r0, r1, r2, r3, uk + row * 128 + ((sg ^ (row & 7)) << 4));
                bT[0][0] = r0; bT[0][1] = r2;
                bT[1][0] = r1; bT[1][1] = r3;
            }
            {
                const int row2 = wn * 24 + 16 + (lane & 7);
                const int sg2  = ks * 2 + ((lane >> 3) & 1);
                uint32_t r0, r1;
                ldsm2(r0, r1, uk + row2 * 128 + ((sg2 ^ (row2 & 7)) << 4));
                bT[2][0] = r0; bT[2][1] = r1;
            }
#pragma unroll
            for (int mi = 0; mi < 3; mi++)
#pragma unroll
                for (int ni = 0; ni < 3; ni++)
                    mma_f16(acc[mi][ni], aT[mi][0], aT[mi][1], aT[mi][2], aT[mi][3],
                            bT[ni][0], bT[ni][1]);
        }
        __syncthreads();
        if (c + 2 < 4) attn_load_qk(sb, st, c + 2, Q, sq, K, sk, b, h, Lq, Lk, tid);
    }

#pragma unroll
    for (int mi = 0; mi < 3; mi++) {
        const int q0 = wm * 48 + mi * 16 + qr;
        const int q1 = q0 + 8;
        const int qok0 = (q0 < Lq) ? qm[b * Lq + q0] : 0;
        const int qok1 = (q1 < Lq) ? qm[b * Lq + q1] : 0;
#pragma unroll
        for (int ni = 0; ni < 3; ni++) {
            const int c0 = wn * 24 + ni * 8 + qc * 2;
            const int c1 = c0 + 1;
            const int k0ok = (km[b * Lk + c0] != 0);
            const int k1ok = (c1 < Lk) ? (km[b * Lk + c1] != 0) : 0;
            if (q0 < Lq) {
                if (c0 < Lk) Ss[q0 * 97 + c0] = (qok0 && k0ok) ? acc[mi][ni][0] * 0.0625f : NEGF;
                if (c1 < Lk) Ss[q0 * 97 + c1] = (qok0 && k1ok) ? acc[mi][ni][1] * 0.0625f : NEGF;
            }
            if (q1 < Lq) {
                if (c0 < Lk) Ss[q1 * 97 + c0] = (qok1 && k0ok) ? acc[mi][ni][2] * 0.0625f : NEGF;
                if (c1 < Lk) Ss[q1 * 97 + c1] = (qok1 && k1ok) ? acc[mi][ni][3] * 0.0625f : NEGF;
            }
        }
    }
    __syncthreads();

    // preload V chunks 0/1
    const int NCv = Lk >> 5;
    {
#pragma unroll
        for (int j = 0; j < 4; j++) {
            const int idx = tid + 256 * j;
            const int kr = idx >> 5, s2 = idx & 31;
            cp16(uV + kr * 512 + (((s2 ^ (kr & 7)) << 4)),
                 V + (size_t)(b * Lk + kr) * sv + h * DHv + s2 * 8);
        }
        CP_COMMIT();
        if (NCv > 1) {
#pragma unroll
            for (int j = 0; j < 4; j++) {
                const int idx = tid + 256 * j;
                const int kr = idx >> 5, s2 = idx & 31;
                cp16(uV + 16384u + kr * 512 + (((s2 ^ (kr & 7)) << 4)),
                     V + (size_t)(b * Lk + 32 + kr) * sv + h * DHv + s2 * 8);
            }
            CP_COMMIT();
        }
    }

    // phase 2: softmax -> P fp16
    {
        const int w = tid >> 5, l = tid & 31;
        for (int r = w; r < Lq; r += 8) {
            float* s = Ss + r * 97;
            float v0 = (l      < Lk) ? s[l]      : -3.4e38f;
            float v1 = (l + 32 < Lk) ? s[l + 32] : -3.4e38f;
            float v2 = (l + 64 < Lk) ? s[l + 64] : -3.4e38f;

            float mx = fmaxf(v0, fmaxf(v1, v2));
#pragma unroll
            for (int o = 16; o; o >>= 1) mx = fmaxf(mx, __shfl_xor_sync(0xffffffffu, mx, o));

            float e0 = (l      < Lk && v0 != NEGF) ? __expf(v0 - mx) : 0.0f;
            float e1 = (l + 32 < Lk && v1 != NEGF) ? __expf(v1 - mx) : 0.0f;
            float e2 = (l + 64 < Lk && v2 != NEGF) ? __expf(v2 - mx) : 0.0f;

            float sum = e0 + e1 + e2;
#pragma unroll
            for (int o = 16; o; o >>= 1) sum += __shfl_xor_sync(0xffffffffu, sum, o);

            const float inv = (sum > 0.0f) ? (1.0f / sum) : 0.0f;
            if (l      < Lk) P[r * 104 + l]      = __float2half(e0 * inv);
            if (l + 32 < Lk) P[r * 104 + l + 32] = __float2half(e1 * inv);
            if (l + 64 < Lk) P[r * 104 + l + 64] = __float2half(e2 * inv);
        }
    }
    __syncthreads();

    // phase 3: AO = P @ V
    float av[3][8][4];
#pragma unroll
    for (int mi = 0; mi < 3; mi++)
#pragma unroll
        for (int nt = 0; nt < 8; nt++)
#pragma unroll
            for (int r = 0; r < 4; r++) av[mi][nt][r] = 0.0f;

    for (int ci = 0; ci < NCv; ci++) {
        const int st = ci & 1;
        if (ci < NCv - 1) CP_WAIT1(); else CP_WAIT0();
        __syncthreads();

        const uint32_t uVs = uV + (uint32_t)st * 16384u;
        const int kk = ci * 32;

#pragma unroll
        for (int ks = 0; ks < 2; ks++) {
            const int k0 = kk + ks * 16;
            uint32_t aP[3][4];
#pragma unroll
            for (int mi = 0; mi < 3; mi++) {
                const int row = wm * 48 + mi * 16 + lane15;
                ldsm4(aP[mi][0], aP[mi][1], aP[mi][2], aP[mi][3],
                      uP + row * 208 + k0 * 2 + hi * 16);
            }
            uint32_t bV[8][2];
#pragma unroll
            for (int t2 = 0; t2 < 4; t2++) {
                const int n0 = wn * 64 + t2 * 16;
                const int kL = ks * 16 + ((lane >> 3) & 1) * 8 + (lane & 7);
                const int sgv = (n0 >> 3) + (lane >> 4);
                uint32_t r0, r1, r2, r3;
                ldsm4t(r0, r1, r2, r3,
                       uVs + kL * 512 + ((sgv ^ (kL & 7)) << 4));
                bV[2 * t2][0]     = r0; bV[2 * t2][1]     = r1;
                bV[2 * t2 + 1][0] = r2; bV[2 * t2 + 1][1] = r3;
            }
#pragma unroll
            for (int mi = 0; mi < 3; mi++)
#pragma unroll
                for (int nt = 0; nt < 8; nt++)
                    mma_f16(av[mi][nt], aP[mi][0], aP[mi][1], aP[mi][2], aP[mi][3],
                            bV[nt][0], bV[nt][1]);
        }
        __syncthreads();
        if (ci + 2 < NCv) {
            const int kk2 = (ci + 2) * 32;
#pragma unroll
            for (int j = 0; j < 4; j++) {
                const int idx = tid + 256 * j;
                const int kr = idx >> 5, s2 = idx & 31;
                cp16(uV + (uint32_t)st * 16384u + kr * 512 + (((s2 ^ (kr & 7)) << 4)),
                     V + (size_t)(b * Lk + kk2 + kr) * sv + h * DHv + s2 * 8);
            }
            CP_COMMIT();
        }
    }

#pragma unroll
    for (int mi = 0; mi < 3; mi++) {
        const int q0 = wm * 48 + mi * 16 + qr;
        const int q1 = q0 + 8;
#pragma unroll
        for (int nt = 0; nt < 8; nt++) {
            const int col = wn * 64 + nt * 8 + qc * 2;
            if (q0 < Lq) {
                __half2 hv = __floats2half2_rn(av[mi][nt][0], av[mi][nt][1]);
                *(__half2*)(AO + (size_t)(b * Lq + q0) * Dv + h * DHv + col) = hv;
            }
            if (q1 < Lq) {
                __half2 hv = __floats2half2_rn(av[mi][nt][2], av[mi][nt][3]);
                *(__half2*)(AO + (size_t)(b * Lq + q1) * Dv + h * DHv + col) = hv;
            }
        }
    }
}

// ---------------------------------------------------------------------------
// LayerNorm over fp16 input; fp32 out and/or fp16 out
// ---------------------------------------------------------------------------
__global__ void __launch_bounds__(256)
ln_kernel(const __half* __restrict__ X, const float* __restrict__ g,
          const float* __restrict__ b, float* __restrict__ Y,
          __half* __restrict__ Y16)
{
    const int row = blockIdx.x;
    const int t   = threadIdx.x;
    const uint2 u = ((const uint2*)(X + (size_t)row * Dv))[t];
    const float2 f0 = __half22float2(*(const __half2*)&u.x);
    const float2 f1 = __half22float2(*(const __half2*)&u.y);
    const float vx = f0.x, vy = f0.y, vz = f1.x, vw = f1.y;

    float s  = vx + vy + vz + vw;
    float ss = vx * vx + vy * vy + vz * vz + vw * vw;

    __shared__ float shs[8], shq[8];
#pragma unroll
    for (int o = 16; o; o >>= 1) {
        s  += __shfl_xor_sync(0xffffffffu, s,  o);
        ss += __shfl_xor_sync(0xffffffffu, ss, o);
    }
    const int w = t >> 5, l = t & 31;
    if (l == 0) { shs[w] = s; shq[w] = ss; }
    __syncthreads();
    float m = 0.0f, q = 0.0f;
#pragma unroll
    for (int i = 0; i < 8; i++) { m += shs[i]; q += shq[i]; }
    m *= (1.0f / Dv);
    q  = q * (1.0f / Dv) - m * m;
    const float r = rsqrtf(q + 1e-3f);

    const float4 gv = ((const float4*)g)[t];
    const float4 bv = ((const float4*)b)[t];
    float4 o;
    o.x = (vx - m) * r * gv.x + bv.x;
    o.y = (vy - m) * r * gv.y + bv.y;
    o.z = (vz - m) * r * gv.z + bv.z;
    o.w = (vw - m) * r * gv.w + bv.w;
    if (Y) ((float4*)(Y + (size_t)row * Dv))[t] = o;
    if (Y16) {
        __half2 h0 = __floats2half2_rn(o.x, o.y);
        __half2 h1 = __floats2half2_rn(o.z, o.w);
        uint2 uo;
        uo.x = *(uint32_t*)&h0;
        uo.y = *(uint32_t*)&h1;
        ((uint2*)(Y16 + (size_t)row * Dv))[t] = uo;
    }
}

// ---------------------------------------------------------------------------
// Host orchestration
// ---------------------------------------------------------------------------
static inline void gemm(cudaStream_t st, const __half* A, int lda,
                        const __half* W, int ldw, const float* bias,
                        __half* C16, int ldc, int M, int N, int K)
{
    dim3 grid(N / 128, M / 128);
    hgemm_kernel<<<grid, 256, SMEM_BYTES, st>>>(A, lda, W, ldw, bias, C16, ldc, M, N, K);
}

extern "C" void kernel_launch(void* const* d_in, const int* in_sizes, int n_in,
                              void* d_out, int out_size)
{
    const float* text_emb  = (const float*)d_in[0];
    const float* image_emb = (const float*)d_in[1];
    const int*   text_mask  = (const int*)d_in[2];
    const int*   image_mask = (const int*)d_in[3];
    const float* W_tp = (const float*)d_in[4];
    const float* b_tp = (const float*)d_in[5];
    const float* W_ip = (const float*)d_in[6];
    const float* b_ip = (const float*)d_in[7];
    const float* ta_Wq = (const float*)d_in[8];
    const float* ta_Wk = (const float*)d_in[9];
    const float* ta_Wv = (const float*)d_in[10];
    const float* ta_Wo = (const float*)d_in[11];
    const float* ia_Wq = (const float*)d_in[12];
    const float* ia_Wk = (const float*)d_in[13];
    const float* ia_Wv = (const float*)d_in[14];
    const float* ia_Wo = (const float*)d_in[15];
    const float* ts_Wq = (const float*)d_in[16];
    const float* ts_Wk = (const float*)d_in[17];
    const float* ts_Wv = (const float*)d_in[18];
    const float* ts_Wo = (const float*)d_in[19];
    const float* is_Wq = (const float*)d_in[20];
    const float* is_Wk = (const float*)d_in[21];
    const float* is_Wv = (const float*)d_in[22];
    const float* is_Wo = (const float*)d_in[23];
    const float* ln_ta_g = (const float*)d_in[24];
    const float* ln_ta_b = (const float*)d_in[25];
    const float* ln_ia_g = (const float*)d_in[26];
    const float* ln_ia_b = (const float*)d_in[27];
    const float* ln_ts_g = (const float*)d_in[28];
    const float* ln_ts_b = (const float*)d_in[29];
    const float* ln_is_g = (const float*)d_in[30];
    const float* ln_is_b = (const float*)d_in[31];

    float* out_text = (float*)d_out;
    float* out_img  = (float*)d_out + (size_t)Bv * LIv * Dv;

    __half *tE16, *iE16, *Wh, *PairVT, *PiVI, *PairI;
    __half *AOT, *XT, *QKVT, *CTh, *AOI, *XI, *QKVI, *CIh;
    float *bcT, *bPI;
    cudaGetSymbolAddress((void**)&tE16,   g_tE16);
    cudaGetSymbolAddress((void**)&iE16,   g_iE16);
    cudaGetSymbolAddress((void**)&Wh,     g_Wh);
    cudaGetSymbolAddress((void**)&PairVT, g_PairVT);
    cudaGetSymbolAddress((void**)&PiVI,   g_PiVI);
    cudaGetSymbolAddress((void**)&PairI,  g_PairI);
    cudaGetSymbolAddress((void**)&AOT,    g_AOT);
    cudaGetSymbolAddress((void**)&XT,     g_XT);
    cudaGetSymbolAddress((void**)&QKVT,   g_QKVT);
    cudaGetSymbolAddress((void**)&CTh,    g_CTh);
    cudaGetSymbolAddress((void**)&AOI,    g_AOI);
    cudaGetSymbolAddress((void**)&XI,     g_XI);
    cudaGetSymbolAddress((void**)&QKVI,   g_QKVI);
    cudaGetSymbolAddress((void**)&CIh,    g_CIh);
    cudaGetSymbolAddress((void**)&bcT,    g_bcT);
    cudaGetSymbolAddress((void**)&bPI,    g_bPI);

    cudaFuncSetAttribute(hgemm_kernel,
                         cudaFuncAttributeMaxDynamicSharedMemorySize, SMEM_BYTES);
    cudaFuncSetAttribute(attn_mma_kernel,
                         cudaFuncAttributeMaxDynamicSharedMemorySize, ATTN_SMEM2);

    static cudaStream_t s1 = nullptr;
    static cudaEvent_t evFork = nullptr, ev2 = nullptr, evT = nullptr,
                       evA = nullptr, evB = nullptr, evJoin = nullptr;
    if (!s1) {
        cudaStreamCreateWithFlags(&s1, cudaStreamNonBlocking);
        cudaEventCreateWithFlags(&evFork, cudaEventDisableTiming);
        cudaEventCreateWithFlags(&ev2, cudaEventDisableTiming);
        cudaEventCreateWithFlags(&evT, cudaEventDisableTiming);
        cudaEventCreateWithFlags(&evA, cudaEventDisableTiming);
        cudaEventCreateWithFlags(&evB, cudaEventDisableTiming);
        cudaEventCreateWithFlags(&evJoin, cudaEventDisableTiming);
    }
    cudaStream_t s0 = (cudaStream_t)0;

    // Wh slot map (1M-half slots) -- ALL natural [K, N] row-major:
    //  0    W_tp16 [1024, 1024]
    //  1-2  pairPt = [ta_Wk | ia_Wq]  [1024, 2048]
    //  3-4  pairPi = [ta_Wq | ia_Wk]  [1024, 2048]
    //  5-8  WiVI   = [W_ip  | ia_Wv]  [2048, 2048]
    //  9    ia_Wo   10-12 isQKV [1024, 3072]   13 is_Wo
    // 14    ta_Wo   15-17 tsQKV [1024, 3072]   18 ts_Wo
    // 19-21 WcVT = [Wc | ta_Wv]  [1024, 3072]
    #define WH(i)  (Wh + ((size_t)(i) << 20))

    // capture-legal fork
    cudaEventRecord(evFork, s0);
    cudaStreamWaitEvent(s1, evFork, 0);

    const int Mt = Bv * LTv;   // 12288
    const int Mi = Bv * LIv;   // 8192

    // ==== s1 prologue FIRST so evT is recorded before s0 waits on it ====
    {
        const int n4t = Bv * LTv * DTv / 4;
        f2h_kernel<<<n4t / 256, 256, 0, s1>>>((const float4*)text_emb, (uint2*)tE16, n4t);
        cudaEventRecord(evT, s1);                 // text embedding ready
    }
    {
        SrcArr2 sw; sw.p[0] = W_ip; sw.p[1] = ia_Wv;       // WiVI [2048,2048]
        f2hs_kernel<SrcArr2><<<dim3(2048, 1, 2), 256, 0, s1>>>(sw, WH(5), 1024, 2048);
        SrcArr2 sp; sp.p[0] = ta_Wq; sp.p[1] = ia_Wk;      // pairPi [1024,2048]
        f2hs_kernel<SrcArr2><<<dim3(1024, 1, 2), 256, 0, s1>>>(sp, WH(3), 1024, 2048);
    }
    bias_pad_kernel<<<8, 256, 0, s1>>>(b_ip, bPI);

    // ==== s0 prologue ====
    {
        const int n4i = Bv * LIv * DIv / 4;
        f2h_kernel<<<n4i / 256, 256, 0, s0>>>((const float4*)image_emb, (uint2*)iE16, n4i);
        cudaEventRecord(ev2, s0);                 // image embedding ready
    }
    f2h_kernel<<<1024, 256, 0, s0>>>((const float4*)W_tp, (uint2*)WH(0), 262144);
    {
        SrcArr2 sp; sp.p[0] = ta_Wk; sp.p[1] = ia_Wq;      // pairPt [1024,2048]
        f2hs_kernel<SrcArr2><<<dim3(1024, 1, 2), 256, 0, s0>>>(sp, WH(1), 1024, 2048);
        SrcArr1 sv; sv.p[0] = ta_Wv;                        // WcVT cols 2048..3071
        f2hs_kernel<SrcArr1><<<dim3(1024, 1, 1), 256, 0, s0>>>(sv, WH(19) + 2048, 0, 3072);
    }
    bias_ct_kernel<<<12, 256, 0, s0>>>(b_tp, ta_Wk, ia_Wq, bcT);
    // compose: Wc[dt, n] = sum_d W_tp[dt, d] * pairPt[d, n]  (into WcVT cols 0..2047)
    gemm(s0, WH(0), 1024, WH(1), 2048, nullptr, WH(19), 3072, 1024, 2048, 1024);
    // PairVT = tE16 @ [Wc | ta_Wv]   (evT already recorded on s1 above)
    cudaStreamWaitEvent(s0, evT, 0);
    gemm(s0, tE16, 1024, WH(19), 3072, bcT, PairVT, 3072, Mt, 3072, 1024);
    cudaEventRecord(evA, s0);
    // branch-I weights (in-stream, consumed by s0 later)
    {
        SrcArr3 sq; sq.p[0] = is_Wq; sq.p[1] = is_Wk; sq.p[2] = is_Wv;
        f2hs_kernel<SrcArr3><<<dim3(1024, 1, 3), 256, 0, s0>>>(sq, WH(10), 1024, 3072);
        SrcArr2 so; so.p[0] = ia_Wo; so.p[1] = is_Wo;
        f2hs_kernel<SrcArr2><<<dim3(1024, 1, 2), 256, 0, s0>>>(so, WH(9), (size_t)4 << 20, 1024);
    }

    // ==== s1: Pi chain (ev2 recorded on s0 above) ====
    cudaStreamWaitEvent(s1, ev2, 0);
    gemm(s1, iE16, 2048, WH(5), 2048, bPI, PiVI, 2048, Mi, 2048, 2048);   // [Pi|VI]
    gemm(s1, PiVI, 2048, WH(3), 2048, nullptr, PairI, 2048, Mi, 2048, 1024); // [QT|KI]
    cudaEventRecord(evB, s1);
    // branch-T weights (in-stream, consumed by s1 later)
    {
        SrcArr3 sq; sq.p[0] = ts_Wq; sq.p[1] = ts_Wk; sq.p[2] = ts_Wv;
        f2hs_kernel<SrcArr3><<<dim3(1024, 1, 3), 256, 0, s1>>>(sq, WH(15), 1024, 3072);
        SrcArr2 so; so.p[0] = ta_Wo; so.p[1] = ts_Wo;
        f2hs_kernel<SrcArr2><<<dim3(1024, 1, 2), 256, 0, s1>>>(so, WH(14), (size_t)4 << 20, 1024);
    }

    const __half* tia_Wo  = WH(9);
    const __half* tis_QKV = WH(10);
    const __half* tis_Wo  = WH(13);
    const __half* tta_Wo  = WH(14);
    const __half* tts_QKV = WH(15);
    const __half* tts_Wo  = WH(18);

    // === branch I (image_att -> out_img) on s0 ===
    cudaStreamWaitEvent(s0, evB, 0);
    attn_mma_kernel<<<BHv, 256, ATTN_SMEM2, s0>>>(PairVT + 1024, 3072, PairI + 1024, 2048,
                                                  PiVI + 1024, 2048, AOI,
                                                  text_mask, image_mask, LTv, LIv);
    gemm(s0, AOI, 1024, tia_Wo, 1024, nullptr, CIh, 1024, Mt, 1024, 1024);
    ln_kernel<<<Mt, 256, 0, s0>>>(CIh, ln_ia_g, ln_ia_b, nullptr, XI);
    gemm(s0, XI, 1024, tis_QKV, 3072, nullptr, QKVI, 3072, Mt, 3072, 1024);
    attn_mma_kernel<<<BHv, 256, ATTN_SMEM2, s0>>>(QKVI, 3072, QKVI + 1024, 3072,
                                                  QKVI + 2048, 3072, AOI,
                                                  text_mask, text_mask, LTv, LTv);
    gemm(s0, AOI, 1024, tis_Wo, 1024, nullptr, CIh, 1024, Mt, 1024, 1024);
    ln_kernel<<<Mt, 256, 0, s0>>>(CIh, ln_is_g, ln_is_b, out_img, nullptr);

    // === branch T (text_att -> out_text) on s1 ===
    cudaStreamWaitEvent(s1, evA, 0);
    attn_mma_kernel<<<BHv, 256, ATTN_SMEM2, s1>>>(PairI, 2048, PairVT, 3072,
                                                  PairVT + 2048, 3072, AOT,
                                                  image_mask, text_mask, LIv, LTv);
    gemm(s1, AOT, 1024, tta_Wo, 1024, nullptr, CTh, 1024, Mi, 1024, 1024);
    ln_kernel<<<Mi, 256, 0, s1>>>(CTh, ln_ta_g, ln_ta_b, nullptr, XT);
    gemm(s1, XT, 1024, tts_QKV, 3072, nullptr, QKVT, 3072, Mi, 3072, 1024);
    attn_mma_kernel<<<BHv, 256, ATTN_SMEM2, s1>>>(QKVT, 3072, QKVT + 1024, 3072,
                                                  QKVT + 2048, 3072, AOT,
                                                  image_mask, image_mask, LIv, LIv);
    gemm(s1, AOT, 1024, tts_Wo, 1024, nullptr, CTh, 1024, Mi, 1024, 1024);
    ln_kernel<<<Mi, 256, 0, s1>>>(CTh, ln_ts_g, ln_ts_b, out_text, nullptr);
    cudaEventRecord(evJoin, s1);

    // join
    cudaStreamWaitEvent(s0, evJoin, 0);
}

// round 15
// speedup vs baseline: 1.1679x; 1.0090x over previous
#include <cuda_runtime.h>
#include <cuda_fp16.h>
#include <cstdint>

// ---------------------------------------------------------------------------
// Problem dims
// ---------------------------------------------------------------------------
#define Bv   128
#define LTv  96
#define LIv  64
#define Dv   1024
#define Hv   4
#define DHv  256
#define DTv  1024
#define DIv  2048
#define BHv  (Bv * Hv)    // 512

#define NEGF (-2147483648.0f)   // -2^31

// ---------------------------------------------------------------------------
// Scratch buffers
// ---------------------------------------------------------------------------
static __device__ __half g_tE16[(size_t)Bv * LTv * DTv];
static __device__ __half g_iE16[(size_t)Bv * LIv * DIv];
static __device__ __half g_PairVT[(size_t)Bv * LTv * 3072];  // tE @ [Wc | ta_Wv] = [KT | QI | VT]
static __device__ __half g_Pi16[(size_t)Bv * LIv * Dv];      // iE @ W_ip + b_ip
static __device__ __half g_VI16[(size_t)Bv * LIv * Dv];      // iE @ ia_Wv
static __device__ __half g_PairI[(size_t)Bv * LIv * 2048];   // Pi @ [ta_Wq | ia_Wk] = [QT | KI]
// branch T (text_att -> out_text), Mi rows
static __device__ __half g_AOT[(size_t)Bv * LIv * Dv];
static __device__ __half g_XT[(size_t)Bv * LIv * Dv];
static __device__ __half g_QKVT[(size_t)Bv * LIv * Dv * 3];
static __device__ __half g_CTh[(size_t)Bv * LIv * Dv];
// branch I (image_att -> out_img), Mt rows
static __device__ __half g_AOI[(size_t)Bv * LTv * Dv];
static __device__ __half g_XI[(size_t)Bv * LTv * Dv];
static __device__ __half g_QKVI[(size_t)Bv * LTv * Dv * 3];
static __device__ __half g_CIh[(size_t)Bv * LTv * Dv];
// weight arena: 22 x 1M-half slots (slot map in kernel_launch); all NATURAL [K,N]
static __device__ __half g_Wh[(size_t)22 * 1024 * 1024];
// composed text bias
static __device__ float g_bcT[3072];

// ---------------------------------------------------------------------------
// PTX helpers
// ---------------------------------------------------------------------------
__device__ __forceinline__ uint32_t smem_u32(const void* p) {
    uint32_t a;
    asm("{ .reg .u64 t; cvta.to.shared.u64 t, %1; cvt.u32.u64 %0, t; }" : "=r"(a) : "l"(p));
    return a;
}
#define CP_COMMIT() asm volatile("cp.async.commit_group;" ::: "memory")
#define CP_WAIT1()  asm volatile("cp.async.wait_group 1;" ::: "memory")
#define CP_WAIT0()  asm volatile("cp.async.wait_group 0;" ::: "memory")

__device__ __forceinline__ void cp16(uint32_t dst, const void* src) {
    asm volatile("cp.async.cg.shared.global [%0], [%1], 16;" :: "r"(dst), "l"(src));
}
__device__ __forceinline__ void cp16z(uint32_t dst, const void* src, int sz) {
    asm volatile("cp.async.cg.shared.global [%0], [%1], 16, %2;"
                 :: "r"(dst), "l"(src), "r"(sz));
}
__device__ __forceinline__ void ldsm4(uint32_t& r0, uint32_t& r1, uint32_t& r2,
                                      uint32_t& r3, uint32_t addr) {
    asm volatile("ldmatrix.sync.aligned.m8n8.x4.shared.b16 {%0,%1,%2,%3}, [%4];"
                 : "=r"(r0), "=r"(r1), "=r"(r2), "=r"(r3) : "r"(addr));
}
__device__ __forceinline__ void ldsm4t(uint32_t& r0, uint32_t& r1, uint32_t& r2,
                                       uint32_t& r3, uint32_t addr) {
    asm volatile("ldmatrix.sync.aligned.m8n8.x4.trans.shared.b16 {%0,%1,%2,%3}, [%4];"
                 : "=r"(r0), "=r"(r1), "=r"(r2), "=r"(r3) : "r"(addr));
}
__device__ __forceinline__ void ldsm2(uint32_t& r0, uint32_t& r1, uint32_t addr) {
    asm volatile("ldmatrix.sync.aligned.m8n8.x2.shared.b16 {%0,%1}, [%2];"
                 : "=r"(r0), "=r"(r1) : "r"(addr));
}
__device__ __forceinline__ void mma_f16(float* c, uint32_t a0, uint32_t a1,
                                        uint32_t a2, uint32_t a3,
                                        uint32_t b0, uint32_t b1) {
    asm volatile(
        "mma.sync.aligned.m16n8k16.row.col.f32.f16.f16.f32 "
        "{%0,%1,%2,%3}, {%4,%5,%6,%7}, {%8,%9}, {%0,%1,%2,%3};"
        : "+f"(c[0]), "+f"(c[1]), "+f"(c[2]), "+f"(c[3])
        : "r"(a0), "r"(a1), "r"(a2), "r"(a3), "r"(b0), "r"(b1));
}

// ---------------------------------------------------------------------------
// fp16 mma GEMM (NT): C16[M,N(ldc)] = A16[M,K(lda)] @ W[K,N(ldw)] (+bias fp32).
// W is NATURAL row-major [K, N] -- B fragments via ldmatrix.trans.
// CTA 128x128, 8 warps, warp tile 64x32, BK=64, 3-stage cp.async.
// ---------------------------------------------------------------------------
#define STAGE_BYTES 32768u
#define NSTAGE      3
#define SMEM_BYTES  (NSTAGE * STAGE_BYTES)

__device__ __forceinline__ void load_chunk_nt(uint32_t sb, int s,
                                              const __half* __restrict__ A, int lda,
                                              const __half* __restrict__ W, int ldw,
                                              int kk, int bm, int bn, int tid)
{
    const uint32_t uA = sb + (uint32_t)s * STAGE_BYTES;
    const uint32_t uB = uA + 16384u;
#pragma unroll
    for (int j = 0; j < 4; j++) {
        int idx = tid + 256 * j;
        int row = idx >> 3, seg = idx & 7;
        cp16(uA + row * 128 + ((seg ^ (row & 7)) << 4),
             A + (size_t)(bm + row) * lda + kk + seg * 8);
    }
#pragma unroll
    for (int j = 0; j < 4; j++) {
        int idx = tid + 256 * j;
        int row = idx >> 4, seg = idx & 15;
        cp16(uB + row * 256 + ((seg ^ (row & 7)) << 4),
             W + (size_t)(kk + row) * ldw + bn + seg * 8);
    }
    CP_COMMIT();
}

__global__ void __launch_bounds__(256, 2)
hgemm_kernel(const __half* __restrict__ A, int lda,
             const __half* __restrict__ W, int ldw,
             const float* __restrict__ bias,
             __half* __restrict__ C16, int ldc,
             int M, int N, int K)
{
    extern __shared__ char smc[];
    const uint32_t sb = smem_u32(smc);
    const int tid  = threadIdx.x;
    const int lane = tid & 31;
    const int warp = tid >> 5;
    const int wm   = warp >> 2;
    const int wn   = warp & 3;
    const int bm   = blockIdx.y * 128;
    const int bn   = blockIdx.x * 128;

    const int lane15 = lane & 15;
    const int hi     = lane >> 4;

    int arow[4];
#pragma unroll
    for (int mi = 0; mi < 4; mi++) arow[mi] = wm * 64 + mi * 16 + lane15;

    float acc[4][4][4];
#pragma unroll
    for (int mi = 0; mi < 4; mi++)
#pragma unroll
        for (int ni = 0; ni < 4; ni++)
#pragma unroll
            for (int r = 0; r < 4; r++) acc[mi][ni][r] = 0.0f;

    const int NC = K >> 6;
    load_chunk_nt(sb, 0, A, lda, W, ldw, 0,  bm, bn, tid);
    load_chunk_nt(sb, 1, A, lda, W, ldw, 64, bm, bn, tid);

    int sc = 0, sl = 2;
    for (int i = 0; i < NC; i++) {
        if (i < NC - 1) CP_WAIT1(); else CP_WAIT0();
        __syncthreads();

        if (i + 2 < NC) {
            load_chunk_nt(sb, sl, A, lda, W, ldw, (i + 2) * 64, bm, bn, tid);
            if (++sl == NSTAGE) sl = 0;
        }

        const uint32_t uA = sb + (uint32_t)sc * STAGE_BYTES;
        const uint32_t uB = uA + 16384u;
        if (++sc == NSTAGE) sc = 0;

#pragma unroll
        for (int ks = 0; ks < 4; ks++) {
            const int sg = ks * 2 + hi;
            uint32_t bf[4][2];
#pragma unroll
            for (int nb = 0; nb < 2; nb++) {
                const int n0  = wn * 32 + nb * 16;
                const int kL  = ks * 16 + ((lane >> 3) & 1) * 8 + (lane & 7);
                const int sgv = (n0 >> 3) + (lane >> 4);
                uint32_t r0, r1, r2, r3;
                ldsm4t(r0, r1, r2, r3,
                       uB + kL * 256 + ((sgv ^ (kL & 7)) << 4));
                bf[nb * 2][0]     = r0; bf[nb * 2][1]     = r1;
                bf[nb * 2 + 1][0] = r2; bf[nb * 2 + 1][1] = r3;
            }
#pragma unroll
            for (int mi = 0; mi < 4; mi++) {
                uint32_t a0, a1, a2, a3;
                ldsm4(a0, a1, a2, a3,
                      uA + arow[mi] * 128 + ((sg ^ (arow[mi] & 7)) << 4));
#pragma unroll
                for (int ni = 0; ni < 4; ni++)
                    mma_f16(acc[mi][ni], a0, a1, a2, a3, bf[ni][0], bf[ni][1]);
            }
        }
    }

    const int qr = lane >> 2, qc = lane & 3;
#pragma unroll
    for (int mi = 0; mi < 4; mi++) {
        const int row = bm + wm * 64 + mi * 16 + qr;
#pragma unroll
        for (int ni = 0; ni < 4; ni++) {
            const int col = bn + wn * 32 + ni * 8 + qc * 2;
            float2 v0 = make_float2(acc[mi][ni][0], acc[mi][ni][1]);
            float2 v1 = make_float2(acc[mi][ni][2], acc[mi][ni][3]);
            if (bias) {
                const float2 bz = *(const float2*)(bias + col);
                v0.x += bz.x; v0.y += bz.y;
                v1.x += bz.x; v1.y += bz.y;
            }
            __half2 h0 = __floats2half2_rn(v0.x, v0.y);
            __half2 h1 = __floats2half2_rn(v1.x, v1.y);
            *(__half2*)(C16 + (size_t)row * ldc + col)       = h0;
            *(__half2*)(C16 + (size_t)(row + 8) * ldc + col) = h1;
        }
    }
}

// ---------------------------------------------------------------------------
// fp32 -> fp16 convert (contiguous)
// ---------------------------------------------------------------------------
__global__ void __launch_bounds__(256)
f2h_kernel(const float4* __restrict__ src, uint2* __restrict__ dst, int n4)
{
    const int i = blockIdx.x * 256 + threadIdx.x;
    if (i < n4) {
        float4 v = src[i];
        __half2 h0 = __floats2half2_rn(v.x, v.y);
        __half2 h1 = __floats2half2_rn(v.z, v.w);
        uint2 o;
        o.x = *(uint32_t*)&h0;
        o.y = *(uint32_t*)&h1;
        dst[i] = o;
    }
}

// ---------------------------------------------------------------------------
// Strided batched fp32->fp16: srcs.p[z] is [K,1024] fp32; row r -> dst +
// z*zStride + r*dstStride.  grid (K, 1, nz), 256 threads/row.
// ---------------------------------------------------------------------------
struct SrcArr1 { const float* p[1]; };
struct SrcArr2 { const float* p[2]; };
struct SrcArr3 { const float* p[3]; };

template <typename SA>
__global__ void __launch_bounds__(256)
f2hs_kernel(SA srcs, __half* __restrict__ dst, size_t zStride, int dstStride)
{
    const int row = blockIdx.x;
    const int z   = blockIdx.z;
    const float4* src = (const float4*)(srcs.p[z] + (size_t)row * 1024);
    __half* d = dst + (size_t)z * zStride + (size_t)row * dstStride;
    const int t = threadIdx.x;
    float4 v = src[t];
    __half2 h0 = __floats2half2_rn(v.x, v.y);
    __half2 h1 = __floats2half2_rn(v.z, v.w);
    uint2 o;
    o.x = *(uint32_t*)&h0;
    o.y = *(uint32_t*)&h1;
    *(uint2*)(d + t * 4) = o;
}

// Composed text bias: bcT[n] = sum_d b[d]*Wp[d,n] (Wp = [W1|W2]) for n<2048; else 0
__global__ void __launch_bounds__(256)
bias_ct_kernel(const float* __restrict__ b, const float* __restrict__ W1,
               const float* __restrict__ W2, float* __restrict__ out)
{
    const int n = blockIdx.x * 256 + threadIdx.x;   // 0..3071
    float s = 0.0f;
    if (n < 2048) {
        const float* W = (n < 1024) ? (W1 + n) : (W2 + n - 1024);
        for (int d = 0; d < 1024; d++) s += b[d] * W[(size_t)d * 1024];
    }
    out[n] = s;
}

// ---------------------------------------------------------------------------
// Tensor-core fused attention (unchanged -- known good).
// ---------------------------------------------------------------------------
#define ATTN_SMEM2 90496

__device__ __forceinline__ void attn_load_qk(uint32_t sb, int st, int c,
        const __half* __restrict__ Q, int sq, const __half* __restrict__ K, int sk,
        int b, int h, int Lq, int Lk, int tid)
{
    const uint32_t uq = sb + (uint32_t)st * 24576u;
    const uint32_t uk = uq + 12288u;
#pragma unroll
    for (int j = 0; j < 3; j++) {
        const int idx = tid + 256 * j;
        const int row = idx >> 3, seg = idx & 7;
        const uint32_t off = row * 128 + ((seg ^ (row & 7)) << 4);
        {
            const int rq = (row < Lq) ? row : 0;
            cp16z(uq + off, Q + (size_t)(b * Lq + rq) * sq + h * DHv + c * 64 + seg * 8,
                  (row < Lq) ? 16 : 0);
        }
        {
            const int rk = (row < Lk) ? row : 0;
            cp16z(uk + off, K + (size_t)(b * Lk + rk) * sk + h * DHv + c * 64 + seg * 8,
                  (row < Lk) ? 16 : 0);
        }
    }
    CP_COMMIT();
}

__global__ void __launch_bounds__(256)
attn_mma_kernel(const __half* __restrict__ Q, int sq,
                const __half* __restrict__ K, int sk,
                const __half* __restrict__ V, int sv,
                __half* __restrict__ AO,
                const int* __restrict__ qm, const int* __restrict__ km,
                int Lq, int Lk)
{
    extern __shared__ char smb[];
    const uint32_t sb = smem_u32(smb);
    float*  Ss = (float*)(smb + 53248);
    __half* P  = (__half*)smb;           // row stride 104 halves
    const uint32_t uP = sb;
    const uint32_t uV = sb + 20480u;

    const int bh = blockIdx.x;
    const int b  = bh >> 2;
    const int h  = bh & 3;
    const int tid  = threadIdx.x;
    const int lane = tid & 31;
    const int warp = tid >> 5;
    const int wm   = warp >> 2;
    const int wn   = warp & 3;
    const int lane15 = lane & 15;
    const int hi     = lane >> 4;
    const int qr = lane >> 2, qc = lane & 3;

    // phase 1: scores = QK^T
    float acc[3][3][4];
#pragma unroll
    for (int mi = 0; mi < 3; mi++)
#pragma unroll
        for (int ni = 0; ni < 3; ni++)
#pragma unroll
            for (int r = 0; r < 4; r++) acc[mi][ni][r] = 0.0f;

    attn_load_qk(sb, 0, 0, Q, sq, K, sk, b, h, Lq, Lk, tid);
    attn_load_qk(sb, 1, 1, Q, sq, K, sk, b, h, Lq, Lk, tid);

    for (int c = 0; c < 4; c++) {
        const int st = c & 1;
        if (c < 3) CP_WAIT1(); else CP_WAIT0();
        __syncthreads();

        const uint32_t uq = sb + (uint32_t)st * 24576u;
        const uint32_t uk = uq + 12288u;

#pragma unroll
        for (int ks = 0; ks < 4; ks++) {
            const int sg = ks * 2 + hi;
            uint32_t aT[3][4];
#pragma unroll
            for (int mi = 0; mi < 3; mi++) {
                const int row = wm * 48 + mi * 16 + lane15;
                ldsm4(aT[mi][0], aT[mi][1], aT[mi][2], aT[mi][3],
                      uq + row * 128 + ((sg ^ (row & 7)) << 4));
            }
            uint32_t bT[3][2];
            {
                const int row = wn * 24 + lane15;
                uint32_t r0, r1, r2, r3;
                ldsm4(r0, r1, r2, r3, uk + row * 128 + ((sg ^ (row & 7)) << 4));
                bT[0][0] = r0; bT[0][1] = r2;
                bT[1][0] = r1; bT[1][1] = r3;
            }
            {
                const int row2 = wn * 24 + 16 + (lane & 7);
                const int sg2  = ks * 2 + ((lane >> 3) & 1);
                uint32_t r0, r1;
                ldsm2(r0, r1, uk + row2 * 128 + ((sg2 ^ (row2 & 7)) << 4));
                bT[2][0] = r0; bT[2][1] = r1;
            }
#pragma unroll
            for (int mi = 0; mi < 3; mi++)
#pragma unroll
                for (int ni = 0; ni < 3; ni++)
                    mma_f16(acc[mi][ni], aT[mi][0], aT[mi][1], aT[mi][2], aT[mi][3],
                            bT[ni][0], bT[ni][1]);
        }
        __syncthreads();
        if (c + 2 < 4) attn_load_qk(sb, st, c + 2, Q, sq, K, sk, b, h, Lq, Lk, tid);
    }

#pragma unroll
    for (int mi = 0; mi < 3; mi++) {
        const int q0 = wm * 48 + mi * 16 + qr;
        const int q1 = q0 + 8;
        const int qok0 = (q0 < Lq) ? qm[b * Lq + q0] : 0;
        const int qok1 = (q1 < Lq) ? qm[b * Lq + q1] : 0;
#pragma unroll
        for (int ni = 0; ni < 3; ni++) {
            const int c0 = wn * 24 + ni * 8 + qc * 2;
            const int c1 = c0 + 1;
            const int k0ok = (km[b * Lk + c0] != 0);
            const int k1ok = (c1 < Lk) ? (km[b * Lk + c1] != 0) : 0;
            if (q0 < Lq) {
                if (c0 < Lk) Ss[q0 * 97 + c0] = (qok0 && k0ok) ? acc[mi][ni][0] * 0.0625f : NEGF;
                if (c1 < Lk) Ss[q0 * 97 + c1] = (qok0 && k1ok) ? acc[mi][ni][1] * 0.0625f : NEGF;
            }
            if (q1 < Lq) {
                if (c0 < Lk) Ss[q1 * 97 + c0] = (qok1 && k0ok) ? acc[mi][ni][2] * 0.0625f : NEGF;
                if (c1 < Lk) Ss[q1 * 97 + c1] = (qok1 && k1ok) ? acc[mi][ni][3] * 0.0625f : NEGF;
            }
        }
    }
    __syncthreads();

    // preload V chunks 0/1
    const int NCv = Lk >> 5;
    {
#pragma unroll
        for (int j = 0; j < 4; j++) {
            const int idx = tid + 256 * j;
            const int kr = idx >> 5, s2 = idx & 31;
            cp16(uV + kr * 512 + (((s2 ^ (kr & 7)) << 4)),
                 V + (size_t)(b * Lk + kr) * sv + h * DHv + s2 * 8);
        }
        CP_COMMIT();
        if (NCv > 1) {
#pragma unroll
            for (int j = 0; j < 4; j++) {
                const int idx = tid + 256 * j;
                const int kr = idx >> 5, s2 = idx & 31;
                cp16(uV + 16384u + kr * 512 + (((s2 ^ (kr & 7)) << 4)),
                     V + (size_t)(b * Lk + 32 + kr) * sv + h * DHv + s2 * 8);
            }
            CP_COMMIT();
        }
    }

    // phase 2: softmax -> P fp16
    {
        const int w = tid >> 5, l = tid & 31;
        for (int r = w; r < Lq; r += 8) {
            float* s = Ss + r * 97;
            float v0 = (l      < Lk) ? s[l]      : -3.4e38f;
            float v1 = (l + 32 < Lk) ? s[l + 32] : -3.4e38f;
            float v2 = (l + 64 < Lk) ? s[l + 64] : -3.4e38f;

            float mx = fmaxf(v0, fmaxf(v1, v2));
#pragma unroll
            for (int o = 16; o; o >>= 1) mx = fmaxf(mx, __shfl_xor_sync(0xffffffffu, mx, o));

            float e0 = (l      < Lk && v0 != NEGF) ? __expf(v0 - mx) : 0.0f;
            float e1 = (l + 32 < Lk && v1 != NEGF) ? __expf(v1 - mx) : 0.0f;
            float e2 = (l + 64 < Lk && v2 != NEGF) ? __expf(v2 - mx) : 0.0f;

            float sum = e0 + e1 + e2;
#pragma unroll
            for (int o = 16; o; o >>= 1) sum += __shfl_xor_sync(0xffffffffu, sum, o);

            const float inv = (sum > 0.0f) ? (1.0f / sum) : 0.0f;
            if (l      < Lk) P[r * 104 + l]      = __float2half(e0 * inv);
            if (l + 32 < Lk) P[r * 104 + l + 32] = __float2half(e1 * inv);
            if (l + 64 < Lk) P[r * 104 + l + 64] = __float2half(e2 * inv);
        }
    }
    __syncthreads();

    // phase 3: AO = P @ V
    float av[3][8][4];
#pragma unroll
    for (int mi = 0; mi < 3; mi++)
#pragma unroll
        for (int nt = 0; nt < 8; nt++)
#pragma unroll
            for (int r = 0; r < 4; r++) av[mi][nt][r] = 0.0f;

    for (int ci = 0; ci < NCv; ci++) {
        const int st = ci & 1;
        if (ci < NCv - 1) CP_WAIT1(); else CP_WAIT0();
        __syncthreads();

        const uint32_t uVs = uV + (uint32_t)st * 16384u;
        const int kk = ci * 32;

#pragma unroll
        for (int ks = 0; ks < 2; ks++) {
            const int k0 = kk + ks * 16;
            uint32_t aP[3][4];
#pragma unroll
            for (int mi = 0; mi < 3; mi++) {
                const int row = wm * 48 + mi * 16 + lane15;
                ldsm4(aP[mi][0], aP[mi][1], aP[mi][2], aP[mi][3],
                      uP + row * 208 + k0 * 2 + hi * 16);
            }
            uint32_t bV[8][2];
#pragma unroll
            for (int t2 = 0; t2 < 4; t2++) {
                const int n0 = wn * 64 + t2 * 16;
                const int kL = ks * 16 + ((lane >> 3) & 1) * 8 + (lane & 7);
                const int sgv = (n0 >> 3) + (lane >> 4);
                uint32_t r0, r1, r2, r3;
                ldsm4t(r0, r1, r2, r3,
                       uVs + kL * 512 + ((sgv ^ (kL & 7)) << 4));
                bV[2 * t2][0]     = r0; bV[2 * t2][1]     = r1;
                bV[2 * t2 + 1][0] = r2; bV[2 * t2 + 1][1] = r3;
            }
#pragma unroll
            for (int mi = 0; mi < 3; mi++)
#pragma unroll
                for (int nt = 0; nt < 8; nt++)
                    mma_f16(av[mi][nt], aP[mi][0], aP[mi][1], aP[mi][2], aP[mi][3],
                            bV[nt][0], bV[nt][1]);
        }
        __syncthreads();
        if (ci + 2 < NCv) {
            const int kk2 = (ci + 2) * 32;
#pragma unroll
            for (int j = 0; j < 4; j++) {
                const int idx = tid + 256 * j;
                const int kr = idx >> 5, s2 = idx & 31;
                cp16(uV + (uint32_t)st * 16384u + kr * 512 + (((s2 ^ (kr & 7)) << 4)),
                     V + (size_t)(b * Lk + kk2 + kr) * sv + h * DHv + s2 * 8);
            }
            CP_COMMIT();
        }
    }

#pragma unroll
    for (int mi = 0; mi < 3; mi++) {
        const int q0 = wm * 48 + mi * 16 + qr;
        const int q1 = q0 + 8;
#pragma unroll
        for (int nt = 0; nt < 8; nt++) {
            const int col = wn * 64 + nt * 8 + qc * 2;
            if (q0 < Lq) {
                __half2 hv = __floats2half2_rn(av[mi][nt][0], av[mi][nt][1]);
                *(__half2*)(AO + (size_t)(b * Lq + q0) * Dv + h * DHv + col) = hv;
            }
            if (q1 < Lq) {
                __half2 hv = __floats2half2_rn(av[mi][nt][2], av[mi][nt][3]);
                *(__half2*)(AO + (size_t)(b * Lq + q1) * Dv + h * DHv + col) = hv;
            }
        }
    }
}

// ---------------------------------------------------------------------------
// LayerNorm over fp16 input; fp32 out and/or fp16 out
// ---------------------------------------------------------------------------
__global__ void __launch_bounds__(256)
ln_kernel(const __half* __restrict__ X, const float* __restrict__ g,
          const float* __restrict__ b, float* __restrict__ Y,
          __half* __restrict__ Y16)
{
    const int row = blockIdx.x;
    const int t   = threadIdx.x;
    const uint2 u = ((const uint2*)(X + (size_t)row * Dv))[t];
    const float2 f0 = __half22float2(*(const __half2*)&u.x);
    const float2 f1 = __half22float2(*(const __half2*)&u.y);
    const float vx = f0.x, vy = f0.y, vz = f1.x, vw = f1.y;

    float s  = vx + vy + vz + vw;
    float ss = vx * vx + vy * vy + vz * vz + vw * vw;

    __shared__ float shs[8], shq[8];
#pragma unroll
    for (int o = 16; o; o >>= 1) {
        s  += __shfl_xor_sync(0xffffffffu, s,  o);
        ss += __shfl_xor_sync(0xffffffffu, ss, o);
    }
    const int w = t >> 5, l = t & 31;
    if (l == 0) { shs[w] = s; shq[w] = ss; }
    __syncthreads();
    float m = 0.0f, q = 0.0f;
#pragma unroll
    for (int i = 0; i < 8; i++) { m += shs[i]; q += shq[i]; }
    m *= (1.0f / Dv);
    q  = q * (1.0f / Dv) - m * m;
    const float r = rsqrtf(q + 1e-3f);

    const float4 gv = ((const float4*)g)[t];
    const float4 bv = ((const float4*)b)[t];
    float4 o;
    o.x = (vx - m) * r * gv.x + bv.x;
    o.y = (vy - m) * r * gv.y + bv.y;
    o.z = (vz - m) * r * gv.z + bv.z;
    o.w = (vw - m) * r * gv.w + bv.w;
    if (Y) ((float4*)(Y + (size_t)row * Dv))[t] = o;
    if (Y16) {
        __half2 h0 = __floats2half2_rn(o.x, o.y);
        __half2 h1 = __floats2half2_rn(o.z, o.w);
        uint2 uo;
        uo.x = *(uint32_t*)&h0;
        uo.y = *(uint32_t*)&h1;
        ((uint2*)(Y16 + (size_t)row * Dv))[t] = uo;
    }
}

// ---------------------------------------------------------------------------
// Host orchestration
// ---------------------------------------------------------------------------
static inline void gemm(cudaStream_t st, const __half* A, int lda,
                        const __half* W, int ldw, const float* bias,
                        __half* C16, int ldc, int M, int N, int K)
{
    dim3 grid(N / 128, M / 128);
    hgemm_kernel<<<grid, 256, SMEM_BYTES, st>>>(A, lda, W, ldw, bias, C16, ldc, M, N, K);
}

extern "C" void kernel_launch(void* const* d_in, const int* in_sizes, int n_in,
                              void* d_out, int out_size)
{
    const float* text_emb  = (const float*)d_in[0];
    const float* image_emb = (const float*)d_in[1];
    const int*   text_mask  = (const int*)d_in[2];
    const int*   image_mask = (const int*)d_in[3];
    const float* W_tp = (const float*)d_in[4];
    const float* b_tp = (const float*)d_in[5];
    const float* W_ip = (const float*)d_in[6];
    const float* b_ip = (const float*)d_in[7];
    const float* ta_Wq = (const float*)d_in[8];
    const float* ta_Wk = (const float*)d_in[9];
    const float* ta_Wv = (const float*)d_in[10];
    const float* ta_Wo = (const float*)d_in[11];
    const float* ia_Wq = (const float*)d_in[12];
    const float* ia_Wk = (const float*)d_in[13];
    const float* ia_Wv = (const float*)d_in[14];
    const float* ia_Wo = (const float*)d_in[15];
    const float* ts_Wq = (const float*)d_in[16];
    const float* ts_Wk = (const float*)d_in[17];
    const float* ts_Wv = (const float*)d_in[18];
    const float* ts_Wo = (const float*)d_in[19];
    const float* is_Wq = (const float*)d_in[20];
    const float* is_Wk = (const float*)d_in[21];
    const float* is_Wv = (const float*)d_in[22];
    const float* is_Wo = (const float*)d_in[23];
    const float* ln_ta_g = (const float*)d_in[24];
    const float* ln_ta_b = (const float*)d_in[25];
    const float* ln_ia_g = (const float*)d_in[26];
    const float* ln_ia_b = (const float*)d_in[27];
    const float* ln_ts_g = (const float*)d_in[28];
    const float* ln_ts_b = (const float*)d_in[29];
    const float* ln_is_g = (const float*)d_in[30];
    const float* ln_is_b = (const float*)d_in[31];

    float* out_text = (float*)d_out;
    float* out_img  = (float*)d_out + (size_t)Bv * LIv * Dv;

    __half *tE16, *iE16, *Wh, *PairVT, *Pi16, *VI16, *PairI;
    __half *AOT, *XT, *QKVT, *CTh, *AOI, *XI, *QKVI, *CIh;
    float *bcT;
    cudaGetSymbolAddress((void**)&tE16,   g_tE16);
    cudaGetSymbolAddress((void**)&iE16,   g_iE16);
    cudaGetSymbolAddress((void**)&Wh,     g_Wh);
    cudaGetSymbolAddress((void**)&PairVT, g_PairVT);
    cudaGetSymbolAddress((void**)&Pi16,   g_Pi16);
    cudaGetSymbolAddress((void**)&VI16,   g_VI16);
    cudaGetSymbolAddress((void**)&PairI,  g_PairI);
    cudaGetSymbolAddress((void**)&AOT,    g_AOT);
    cudaGetSymbolAddress((void**)&XT,     g_XT);
    cudaGetSymbolAddress((void**)&QKVT,   g_QKVT);
    cudaGetSymbolAddress((void**)&CTh,    g_CTh);
    cudaGetSymbolAddress((void**)&AOI,    g_AOI);
    cudaGetSymbolAddress((void**)&XI,     g_XI);
    cudaGetSymbolAddress((void**)&QKVI,   g_QKVI);
    cudaGetSymbolAddress((void**)&CIh,    g_CIh);
    cudaGetSymbolAddress((void**)&bcT,    g_bcT);

    cudaFuncSetAttribute(hgemm_kernel,
                         cudaFuncAttributeMaxDynamicSharedMemorySize, SMEM_BYTES);
    cudaFuncSetAttribute(attn_mma_kernel,
                         cudaFuncAttributeMaxDynamicSharedMemorySize, ATTN_SMEM2);

    static cudaStream_t s1 = nullptr;
    static cudaEvent_t evFork = nullptr, ev2 = nullptr, evT = nullptr,
                       evA = nullptr, evB = nullptr, evJoin = nullptr;
    if (!s1) {
        cudaStreamCreateWithFlags(&s1, cudaStreamNonBlocking);
        cudaEventCreateWithFlags(&evFork, cudaEventDisableTiming);
        cudaEventCreateWithFlags(&ev2, cudaEventDisableTiming);
        cudaEventCreateWithFlags(&evT, cudaEventDisableTiming);
        cudaEventCreateWithFlags(&evA, cudaEventDisableTiming);
        cudaEventCreateWithFlags(&evB, cudaEventDisableTiming);
        cudaEventCreateWithFlags(&evJoin, cudaEventDisableTiming);
    }
    cudaStream_t s0 = (cudaStream_t)0;

    // Wh slot map (1M-half slots) -- ALL natural [K, N] row-major:
    //  0    W_tp16 [1024, 1024]
    //  1-2  pairPt = [ta_Wk | ia_Wq]  [1024, 2048]
    //  3-4  pairPi = [ta_Wq | ia_Wk]  [1024, 2048]
    //  5-6  W_ip16 [2048, 1024]      7-8  ia_Wv16 [2048, 1024]
    //  9    ia_Wo   10-12 isQKV [1024, 3072]   13 is_Wo
    // 14    ta_Wo   15-17 tsQKV [1024, 3072]   18 ts_Wo
    // 19-21 WcVT = [Wc | ta_Wv]  [1024, 3072]
    #define WH(i)  (Wh + ((size_t)(i) << 20))

    // capture-legal fork
    cudaEventRecord(evFork, s0);
    cudaStreamWaitEvent(s1, evFork, 0);

    const int Mt = Bv * LTv;   // 12288
    const int Mi = Bv * LIv;   // 8192

    // ==== s1 prologue FIRST (records evT before s0 waits) ====
    {
        const int n4t = Bv * LTv * DTv / 4;
        f2h_kernel<<<n4t / 256, 256, 0, s1>>>((const float4*)text_emb, (uint2*)tE16, n4t);
        cudaEventRecord(evT, s1);                 // text embedding ready
    }
    {
        SrcArr1 sw; sw.p[0] = W_ip;                          // W_ip16 [2048,1024]
        f2hs_kernel<SrcArr1><<<dim3(2048, 1, 1), 256, 0, s1>>>(sw, WH(5), 0, 1024);
        SrcArr2 sp; sp.p[0] = ta_Wq; sp.p[1] = ia_Wk;        // pairPi [1024,2048]
        f2hs_kernel<SrcArr2><<<dim3(1024, 1, 2), 256, 0, s1>>>(sp, WH(3), 1024, 2048);
    }

    // ==== s0 prologue ====
    {
        const int n4i = Bv * LIv * DIv / 4;
        f2h_kernel<<<n4i / 256, 256, 0, s0>>>((const float4*)image_emb, (uint2*)iE16, n4i);
        cudaEventRecord(ev2, s0);                 // image embedding ready
    }
    f2h_kernel<<<1024, 256, 0, s0>>>((const float4*)W_tp, (uint2*)WH(0), 262144);
    {
        SrcArr2 sp; sp.p[0] = ta_Wk; sp.p[1] = ia_Wq;        // pairPt [1024,2048]
        f2hs_kernel<SrcArr2><<<dim3(1024, 1, 2), 256, 0, s0>>>(sp, WH(1), 1024, 2048);
        SrcArr1 sv; sv.p[0] = ta_Wv;                          // WcVT cols 2048..3071
        f2hs_kernel<SrcArr1><<<dim3(1024, 1, 1), 256, 0, s0>>>(sv, WH(19) + 2048, 0, 3072);
        SrcArr1 si; si.p[0] = ia_Wv;                          // ia_Wv16 [2048,1024]
        f2hs_kernel<SrcArr1><<<dim3(2048, 1, 1), 256, 0, s0>>>(si, WH(7), 0, 1024);
    }
    bias_ct_kernel<<<12, 256, 0, s0>>>(b_tp, ta_Wk, ia_Wq, bcT);
    // compose: Wc[dt, n] = sum_d W_tp[dt, d] * pairPt[d, n]
    gemm(s0, WH(0), 1024, WH(1), 2048, nullptr, WH(19), 3072, 1024, 2048, 1024);
    // PairVT = tE16 @ [Wc | ta_Wv]
    cudaStreamWaitEvent(s0, evT, 0);
    gemm(s0, tE16, 1024, WH(19), 3072, bcT, PairVT, 3072, Mt, 3072, 1024);
    cudaEventRecord(evA, s0);
    // VI on s0 (iE16 is s0-produced; no event needed). Overlaps s1's attn(T).
    gemm(s0, iE16, 2048, WH(7), 1024, nullptr, VI16, 1024, Mi, 1024, 2048);
    // branch-I weights (in-stream, consumed by s0 later)
    {
        SrcArr3 sq; sq.p[0] = is_Wq; sq.p[1] = is_Wk; sq.p[2] = is_Wv;
        f2hs_kernel<SrcArr3><<<dim3(1024, 1, 3), 256, 0, s0>>>(sq, WH(10), 1024, 3072);
        SrcArr2 so; so.p[0] = ia_Wo; so.p[1] = is_Wo;
        f2hs_kernel<SrcArr2><<<dim3(1024, 1, 2), 256, 0, s0>>>(so, WH(9), (size_t)4 << 20, 1024);
    }

    // ==== s1: Pi chain (ev2 recorded on s0 above) ====
    cudaStreamWaitEvent(s1, ev2, 0);
    gemm(s1, iE16, 2048, WH(5), 1024, b_ip, Pi16, 1024, Mi, 1024, 2048);     // Pi
    gemm(s1, Pi16, 1024, WH(3), 2048, nullptr, PairI, 2048, Mi, 2048, 1024); // [QT|KI]
    cudaEventRecord(evB, s1);
    // branch-T weights (in-stream, consumed by s1 later)
    {
        SrcArr3 sq; sq.p[0] = ts_Wq; sq.p[1] = ts_Wk; sq.p[2] = ts_Wv;
        f2hs_kernel<SrcArr3><<<dim3(1024, 1, 3), 256, 0, s1>>>(sq, WH(15), 1024, 3072);
        SrcArr2 so; so.p[0] = ta_Wo; so.p[1] = ts_Wo;
        f2hs_kernel<SrcArr2><<<dim3(1024, 1, 2), 256, 0, s1>>>(so, WH(14), (size_t)4 << 20, 1024);
    }

    const __half* tia_Wo  = WH(9);
    const __half* tis_QKV = WH(10);
    const __half* tis_Wo  = WH(13);
    const __half* tta_Wo  = WH(14);
    const __half* tts_QKV = WH(15);
    const __half* tts_Wo  = WH(18);

    // === branch T (text_att -> out_text) on s1 — starts right after PairI ===
    cudaStreamWaitEvent(s1, evA, 0);
    attn_mma_kernel<<<BHv, 256, ATTN_SMEM2, s1>>>(PairI, 2048, PairVT, 3072,
                                                  PairVT + 2048, 3072, AOT,
                                                  image_mask, text_mask, LIv, LTv);
    gemm(s1, AOT, 1024, tta_Wo, 1024, nullptr, CTh, 1024, Mi, 1024, 1024);
    ln_kernel<<<Mi, 256, 0, s1>>>(CTh, ln_ta_g, ln_ta_b, nullptr, XT);
    gemm(s1, XT, 1024, tts_QKV, 3072, nullptr, QKVT, 3072, Mi, 3072, 1024);
    attn_mma_kernel<<<BHv, 256, ATTN_SMEM2, s1>>>(QKVT, 3072, QKVT + 1024, 3072,
                                                  QKVT + 2048, 3072, AOT,
                                                  image_mask, image_mask, LIv, LIv);
    gemm(s1, AOT, 1024, tts_Wo, 1024, nullptr, CTh, 1024, Mi, 1024, 1024);
    ln_kernel<<<Mi, 256, 0, s1>>>(CTh, ln_ts_g, ln_ts_b, out_text, nullptr);
    cudaEventRecord(evJoin, s1);

    // === branch I (image_att -> out_img) on s0 ===
    cudaStreamWaitEvent(s0, evB, 0);
    attn_mma_kernel<<<BHv, 256, ATTN_SMEM2, s0>>>(PairVT + 1024, 3072, PairI + 1024, 2048,
                                                  VI16, 1024, AOI,
                                                  text_mask, image_mask, LTv, LIv);
    gemm(s0, AOI, 1024, tia_Wo, 1024, nullptr, CIh, 1024, Mt, 1024, 1024);
    ln_kernel<<<Mt, 256, 0, s0>>>(CIh, ln_ia_g, ln_ia_b, nullptr, XI);
    gemm(s0, XI, 1024, tis_QKV, 3072, nullptr, QKVI, 3072, Mt, 3072, 1024);
    attn_mma_kernel<<<BHv, 256, ATTN_SMEM2, s0>>>(QKVI, 3072, QKVI + 1024, 3072,
                                                  QKVI + 2048, 3072, AOI,
                                                  text_mask, text_mask, LTv, LTv);
    gemm(s0, AOI, 1024, tis_Wo, 1024, nullptr, CIh, 1024, Mt, 1024, 1024);
    ln_kernel<<<Mt, 256, 0, s0>>>(CIh, ln_is_g, ln_is_b, out_img, nullptr);

    // join
    cudaStreamWaitEvent(s0, evJoin, 0);
}